// round 1
// baseline (speedup 1.0000x reference)
#include <cuda_runtime.h>
#include <cuda_fp16.h>
#include <math.h>
#include <float.h>

// ---------------- problem constants ----------------
#define S_   1024
#define D_   1024
#define H_   16
#define KV_  4
#define HD_  64
#define KVD_ 256
#define FF_  4096
#define L_   8
#define V_   50257
#define EPS_ 1.1920928955078125e-07f

// ---------------- device scratch (static; no runtime alloc) ----------------
__device__ float g_wq [L_ * D_   * D_ ];
__device__ float g_wk [L_ * KVD_ * D_ ];
__device__ float g_wv [L_ * KVD_ * D_ ];
__device__ float g_wo [L_ * D_   * D_ ];
__device__ float g_wfc[L_ * FF_  * D_ ];
__device__ float g_wpr[L_ * D_   * FF_];
__device__ float g_lm [(size_t)V_ * D_];
__device__ float g_x  [S_ * D_ ];
__device__ float g_h  [S_ * D_ ];
__device__ float g_q  [S_ * D_ ];
__device__ float g_k  [S_ * KVD_];
__device__ float g_v  [S_ * KVD_];
__device__ float g_sc [(size_t)H_ * S_ * S_];
__device__ float g_att[S_ * D_ ];
__device__ float g_ff [S_ * FF_];

// ---------------- fake-quant (per-row int8 with quantile clip) ----------------
// clip = quantile(|w|, 0.9999984) over row of length n. For n in {1024,4096}
// the index q*(n-1) lands between the 2nd-largest and largest |w|, so we only
// need the top-2 abs values per row.
__global__ void quant_kernel(const float* __restrict__ W, float* __restrict__ DQ, int n)
{
    int row = blockIdx.x;
    const float* w = W + (size_t)row * n;
    float* dq = DQ + (size_t)row * n;
    int tid = threadIdx.x;

    float m1 = 0.f, m2 = 0.f;
    for (int i = tid; i < n; i += 256) {
        float a = fabsf(w[i]);
        if (a > m1) { m2 = m1; m1 = a; }
        else if (a > m2) { m2 = a; }
    }
    __shared__ float s1[256], s2[256];
    s1[tid] = m1; s2[tid] = m2;
    __syncthreads();
    for (int off = 128; off; off >>= 1) {
        if (tid < off) {
            float a1 = s1[tid], a2 = s2[tid];
            float b1 = s1[tid + off], b2 = s2[tid + off];
            float n1 = fmaxf(a1, b1);
            float n2 = fmaxf(fminf(a1, b1), fmaxf(a2, b2));
            s1[tid] = n1; s2[tid] = n2;
        }
        __syncthreads();
    }
    __shared__ float sh_clip, sh_scale, sh_s16;
    if (tid == 0) {
        float M1 = s1[0], M2 = s2[0];
        float idxf = 0.9999984f * (float)(n - 1);   // fp32, matching jnp
        float frac = idxf - (float)(n - 2);
        float clip = M2 * (1.0f - frac) + M1 * frac;
        float scale = fmaxf(__fdiv_rn(clip, 127.0f), 1.0f / 127.0f);
        sh_clip = clip;
        sh_scale = scale;
        sh_s16 = __half2float(__float2half_rn(scale));
    }
    __syncthreads();
    float clip = sh_clip, scale = sh_scale, s16 = sh_s16;
    for (int i = tid; i < n; i += 256) {
        float v = w[i];
        float c = fminf(fmaxf(v, -clip), clip);
        float q = rintf(__fdiv_rn(c, scale));       // round-half-even
        q = fminf(fmaxf(q, -127.f), 127.f);
        dq[i] = q * s16;
    }
}

// ---------------- embedding gather ----------------
__global__ void embed_kernel(const int* __restrict__ idx, const float* __restrict__ emb,
                             float* __restrict__ x)
{
    int i = blockIdx.x * blockDim.x + threadIdx.x;   // over S_*D_
    int s = i >> 10, d = i & 1023;
    x[i] = emb[(size_t)idx[s] * D_ + d];
}

// ---------------- rmsnorm over last dim d (row per block) ----------------
__global__ void rmsnorm_kernel(const float* __restrict__ x, float* __restrict__ out, int d)
{
    int row = blockIdx.x;
    const float* xr = x + (size_t)row * d;
    float* orow = out + (size_t)row * d;
    int tid = threadIdx.x;
    float ss = 0.f;
    for (int i = tid; i < d; i += 256) { float v = xr[i]; ss += v * v; }
    __shared__ float sh[256];
    sh[tid] = ss; __syncthreads();
    for (int off = 128; off; off >>= 1) {
        if (tid < off) sh[tid] += sh[tid + off];
        __syncthreads();
    }
    float r = rsqrtf(sh[0] / (float)d + EPS_);
    for (int i = tid; i < d; i += 256) orow[i] = xr[i] * r;
}

// ---------------- per-head RMS + RoPE + gain (one warp per (s,head)) ----------------
__global__ void qkpost_kernel(float* __restrict__ x, const float* __restrict__ gain,
                              int nh, int stride, int use_gain)
{
    int warp = (blockIdx.x * blockDim.x + threadIdx.x) >> 5;
    int lane = threadIdx.x & 31;
    int s = warp / nh, h = warp % nh;
    if (s >= S_) return;
    float* base = x + (size_t)s * stride + h * HD_;
    float e0 = base[lane], e1 = base[lane + 32];
    float ss = e0 * e0 + e1 * e1;
    #pragma unroll
    for (int o = 16; o; o >>= 1) ss += __shfl_xor_sync(0xffffffffu, ss, o);
    float r = rsqrtf(ss * (1.f / 64.f) + EPS_);
    e0 *= r; e1 *= r;
    // rope: pair (lane, lane+32); inv_freq computed in double (fast-math safe)
    float inv = (float)exp(-((double)lane / 32.0) * 9.210340371976184);  // ln(10000)
    float f = (float)s * inv;
    float c  = (float)cos((double)f);
    float sn = (float)sin((double)f);
    float o0 =  e0 * c + e1 * sn;
    float o1 = -e0 * sn + e1 * c;
    float g = use_gain ? gain[h] : 1.0f;
    base[lane]      = o0 * g;
    base[lane + 32] = o1 * g;
}

// ---------------- attention scores (causal, lower-triangle tiles only) ----------------
__global__ void scores_kernel(const float* __restrict__ q, const float* __restrict__ k,
                              float* __restrict__ sc)
{
    int bi = blockIdx.y, bj = blockIdx.x, h = blockIdx.z;
    if (bj * 16 > bi * 16 + 15) return;              // fully masked tile
    int kvh = h >> 2;                                // rep = H/KV = 4
    __shared__ float qs[16][65];
    __shared__ float ks[16][65];
    int tx = threadIdx.x, ty = threadIdx.y;
    int tid = ty * 16 + tx;
    {
        int r = tid >> 4, c4 = (tid & 15) * 4;
        const float4 qv = *(const float4*)(q + (size_t)(bi * 16 + r) * D_   + h   * HD_ + c4);
        const float4 kv = *(const float4*)(k + (size_t)(bj * 16 + r) * KVD_ + kvh * HD_ + c4);
        qs[r][c4] = qv.x; qs[r][c4+1] = qv.y; qs[r][c4+2] = qv.z; qs[r][c4+3] = qv.w;
        ks[r][c4] = kv.x; ks[r][c4+1] = kv.y; ks[r][c4+2] = kv.z; ks[r][c4+3] = kv.w;
    }
    __syncthreads();
    int gi = bi * 16 + ty, gj = bj * 16 + tx;
    if (gj > gi) return;
    float acc = 0.f;
    #pragma unroll
    for (int d = 0; d < 64; d++) acc += qs[ty][d] * ks[tx][d];
    sc[((size_t)h * S_ + gi) * S_ + gj] = acc * 0.125f;   // 1/sqrt(64)
}

// ---------------- causal softmax (row per block); zeroes masked tail ----------------
__global__ void softmax_kernel(float* __restrict__ sc)
{
    int i = blockIdx.x, h = blockIdx.y;
    float* row = sc + ((size_t)h * S_ + i) * S_;
    int len = i + 1;
    int tid = threadIdx.x;
    __shared__ float sh[256];
    float m = -FLT_MAX;
    for (int j = tid; j < len; j += 256) m = fmaxf(m, row[j]);
    sh[tid] = m; __syncthreads();
    for (int off = 128; off; off >>= 1) {
        if (tid < off) sh[tid] = fmaxf(sh[tid], sh[tid + off]);
        __syncthreads();
    }
    float M = sh[0];
    __syncthreads();
    float sum = 0.f;
    for (int j = tid; j < len; j += 256) {
        float e = expf(row[j] - M);
        row[j] = e;
        sum += e;
    }
    sh[tid] = sum; __syncthreads();
    for (int off = 128; off; off >>= 1) {
        if (tid < off) sh[tid] += sh[tid + off];
        __syncthreads();
    }
    float inv = 1.0f / sh[0];
    for (int j = tid; j < S_; j += 256)
        row[j] = (j < len) ? row[j] * inv : 0.0f;
}

// ---------------- AV: y[i, h*64+d] = sum_j p[h,i,j] * v[j, kvh*64+d] ----------------
__global__ void av_kernel(const float* __restrict__ p, const float* __restrict__ v,
                          float* __restrict__ y)
{
    int h = blockIdx.y, kvh = h >> 2;
    int tx = threadIdx.x;               // d: 0..63
    int ty = threadIdx.y;               // row in block: 0..3
    int tid = ty * 64 + tx;
    int i = blockIdx.x * 4 + ty;
    __shared__ float vs[64][65];
    __shared__ float ps[4][64];
    int ntiles = (blockIdx.x * 4 + 3) / 64 + 1;
    float acc = 0.f;
    const float* prow = p + ((size_t)h * S_ + i) * S_;
    for (int jt = 0; jt < ntiles; jt++) {
        #pragma unroll
        for (int t = 0; t < 16; t++) {
            int idx = tid + t * 256;
            int jj = idx >> 6, d = idx & 63;
            vs[jj][d] = v[(size_t)(jt * 64 + jj) * KVD_ + kvh * HD_ + d];
        }
        ps[ty][tx] = prow[jt * 64 + tx];   // zeros beyond row length (softmax wrote them)
        __syncthreads();
        #pragma unroll
        for (int jj = 0; jj < 64; jj++) acc += ps[ty][jj] * vs[jj][tx];
        __syncthreads();
    }
    y[(size_t)i * D_ + h * HD_ + tx] = acc;
}

// ---------------- SGEMM: C[M,N] = A[M,K] @ op(B), fused epilogue ----------------
// BT=true : B is [N,K] row-major (NT gemm, used for all W^T products)
// EPI: 0=none, 1=add residual, 2=relu(x)^2
template<bool BT, int EPI>
__global__ void sgemm_kernel(const float* __restrict__ A, const float* __restrict__ B,
                             const float* __restrict__ Res, float* __restrict__ C,
                             int M, int N, int K)
{
    const int BM = 128, BN = 128, BK = 8;
    __shared__ float As[BK][BM];
    __shared__ float Bs[BK][BN];
    int tid = threadIdx.x;
    int tx = tid & 15, ty = tid >> 4;
    int row0 = blockIdx.y * BM, col0 = blockIdx.x * BN;
    float acc[8][8] = {};

    for (int k0 = 0; k0 < K; k0 += BK) {
        #pragma unroll
        for (int t = 0; t < 4; t++) {
            int idx = tid + t * 256;
            int r = idx >> 3, kk = idx & 7;
            int gr = row0 + r;
            As[kk][r] = (gr < M) ? A[(size_t)gr * K + k0 + kk] : 0.f;
        }
        if (BT) {
            #pragma unroll
            for (int t = 0; t < 4; t++) {
                int idx = tid + t * 256;
                int c = idx >> 3, kk = idx & 7;
                int gc = col0 + c;
                Bs[kk][c] = (gc < N) ? B[(size_t)gc * K + k0 + kk] : 0.f;
            }
        } else {
            #pragma unroll
            for (int t = 0; t < 4; t++) {
                int idx = tid + t * 256;
                int kk = idx >> 7, c = idx & 127;
                int gc = col0 + c;
                Bs[kk][c] = (gc < N) ? B[(size_t)(k0 + kk) * N + gc] : 0.f;
            }
        }
        __syncthreads();
        #pragma unroll
        for (int kk = 0; kk < BK; kk++) {
            float ra[8], rb[8];
            #pragma unroll
            for (int i = 0; i < 8; i++) ra[i] = As[kk][ty * 8 + i];
            #pragma unroll
            for (int j = 0; j < 8; j++) rb[j] = Bs[kk][tx * 8 + j];
            #pragma unroll
            for (int i = 0; i < 8; i++)
                #pragma unroll
                for (int j = 0; j < 8; j++)
                    acc[i][j] += ra[i] * rb[j];
        }
        __syncthreads();
    }
    #pragma unroll
    for (int i = 0; i < 8; i++) {
        int gr = row0 + ty * 8 + i;
        if (gr >= M) continue;
        #pragma unroll
        for (int j = 0; j < 8; j++) {
            int gc = col0 + tx * 8 + j;
            if (gc >= N) continue;
            size_t o = (size_t)gr * N + gc;
            float val = acc[i][j];
            if (EPI == 1) val += Res[o];
            if (EPI == 2) { val = fmaxf(val, 0.f); val = val * val; }
            C[o] = val;
        }
    }
}

// ---------------- host orchestration ----------------
extern "C" void kernel_launch(void* const* d_in, const int* in_sizes, int n_in,
                              void* d_out, int out_size)
{
    (void)in_sizes; (void)n_in; (void)out_size;
    const int*   idx = (const int*)  d_in[0];
    const float* emb = (const float*)d_in[1];
    const float* wq  = (const float*)d_in[2];
    const float* wk  = (const float*)d_in[3];
    const float* wv  = (const float*)d_in[4];
    const float* wo  = (const float*)d_in[5];
    const float* qg  = (const float*)d_in[6];
    const float* wfc = (const float*)d_in[7];
    const float* wpr = (const float*)d_in[8];
    const float* lm  = (const float*)d_in[9];
    float* out = (float*)d_out;

    float *p_wq, *p_wk, *p_wv, *p_wo, *p_wfc, *p_wpr, *p_lm;
    float *p_x, *p_h, *p_q, *p_k, *p_v, *p_sc, *p_att, *p_ff;
    cudaGetSymbolAddress((void**)&p_wq,  g_wq);
    cudaGetSymbolAddress((void**)&p_wk,  g_wk);
    cudaGetSymbolAddress((void**)&p_wv,  g_wv);
    cudaGetSymbolAddress((void**)&p_wo,  g_wo);
    cudaGetSymbolAddress((void**)&p_wfc, g_wfc);
    cudaGetSymbolAddress((void**)&p_wpr, g_wpr);
    cudaGetSymbolAddress((void**)&p_lm,  g_lm);
    cudaGetSymbolAddress((void**)&p_x,   g_x);
    cudaGetSymbolAddress((void**)&p_h,   g_h);
    cudaGetSymbolAddress((void**)&p_q,   g_q);
    cudaGetSymbolAddress((void**)&p_k,   g_k);
    cudaGetSymbolAddress((void**)&p_v,   g_v);
    cudaGetSymbolAddress((void**)&p_sc,  g_sc);
    cudaGetSymbolAddress((void**)&p_att, g_att);
    cudaGetSymbolAddress((void**)&p_ff,  g_ff);

    // 1) fake-quant all weights
    quant_kernel<<<L_ * D_,   256>>>(wq,  p_wq,  D_);
    quant_kernel<<<L_ * KVD_, 256>>>(wk,  p_wk,  D_);
    quant_kernel<<<L_ * KVD_, 256>>>(wv,  p_wv,  D_);
    quant_kernel<<<L_ * D_,   256>>>(wo,  p_wo,  D_);
    quant_kernel<<<L_ * FF_,  256>>>(wfc, p_wfc, D_);
    quant_kernel<<<L_ * D_,   256>>>(wpr, p_wpr, FF_);
    quant_kernel<<<V_,        256>>>(lm,  p_lm,  D_);

    // 2) embedding
    embed_kernel<<<(S_ * D_) / 256, 256>>>(idx, emb, p_x);

    // 3) transformer blocks
    for (int l = 0; l < L_; l++) {
        rmsnorm_kernel<<<S_, 256>>>(p_x, p_h, D_);

        sgemm_kernel<true, 0><<<dim3(D_ / 128,   S_ / 128), 256>>>(p_h, p_wq + (size_t)l * D_ * D_,   nullptr, p_q, S_, D_,   D_);
        sgemm_kernel<true, 0><<<dim3(KVD_ / 128, S_ / 128), 256>>>(p_h, p_wk + (size_t)l * KVD_ * D_, nullptr, p_k, S_, KVD_, D_);
        sgemm_kernel<true, 0><<<dim3(KVD_ / 128, S_ / 128), 256>>>(p_h, p_wv + (size_t)l * KVD_ * D_, nullptr, p_v, S_, KVD_, D_);

        qkpost_kernel<<<(S_ * H_)  / 4, 128>>>(p_q, qg + l * H_, H_,  D_,   1);
        qkpost_kernel<<<(S_ * KV_) / 4, 128>>>(p_k, nullptr,     KV_, KVD_, 0);

        scores_kernel<<<dim3(S_ / 16, S_ / 16, H_), dim3(16, 16)>>>(p_q, p_k, p_sc);
        softmax_kernel<<<dim3(S_, H_), 256>>>(p_sc);
        av_kernel<<<dim3(S_ / 4, H_), dim3(64, 4)>>>(p_sc, p_v, p_att);

        sgemm_kernel<true, 1><<<dim3(D_ / 128, S_ / 128), 256>>>(p_att, p_wo + (size_t)l * D_ * D_, p_x, p_x, S_, D_, D_);

        rmsnorm_kernel<<<S_, 256>>>(p_x, p_h, D_);
        sgemm_kernel<true, 2><<<dim3(FF_ / 128, S_ / 128), 256>>>(p_h,  p_wfc + (size_t)l * FF_ * D_, nullptr, p_ff, S_, FF_, D_);
        sgemm_kernel<true, 1><<<dim3(D_ / 128,  S_ / 128), 256>>>(p_ff, p_wpr + (size_t)l * D_ * FF_, p_x,     p_x,  S_, D_,  FF_);
    }

    // 4) final norm + lm_head
    rmsnorm_kernel<<<S_, 256>>>(p_x, p_h, D_);
    sgemm_kernel<true, 0><<<dim3((V_ + 127) / 128, S_ / 128), 256>>>(p_h, p_lm, nullptr, out, S_, V_, D_);
}

// round 5
// speedup vs baseline: 3.8079x; 3.8079x over previous
#include <cuda_runtime.h>
#include <cuda_fp16.h>
#include <cuda_bf16.h>
#include <stdint.h>
#include <cstdint>
#include <math.h>
#include <float.h>

typedef unsigned int u32;

#define S_   1024
#define D_   1024
#define H_   16
#define KV_  4
#define HD_  64
#define KVD_ 256
#define FF_  4096
#define L_   8
#define V_   50257
#define VPAD_ 50304
#define QKVD_ 1536
#define EPS_ 1.1920928955078125e-07f

// ---------------- device globals (all scratch lives here) ----------------
__device__ __nv_bfloat16 g_qw  [L_ * QKVD_ * D_];
__device__ __nv_bfloat16 g_qwo [L_ * D_   * D_ ];
__device__ __nv_bfloat16 g_qwfc[L_ * FF_  * D_ ];
__device__ __nv_bfloat16 g_qwpr[L_ * D_   * FF_];
__device__ __nv_bfloat16 g_qlm [(size_t)VPAD_ * D_];
__device__ float g_sqkv[L_ * QKVD_];
__device__ float g_swo [L_ * D_ ];
__device__ float g_swfc[L_ * FF_];
__device__ float g_swpr[L_ * D_ ];
__device__ float g_slm [VPAD_];

__device__ float g_x  [S_ * D_ ];
__device__ __nv_bfloat16 g_hhi[S_ * D_ ];
__device__ __nv_bfloat16 g_hlo[S_ * D_ ];
__device__ float g_qkv[S_ * QKVD_];
__device__ float g_sc [(size_t)H_ * S_ * S_];
__device__ __nv_bfloat16 g_atthi[S_ * D_];
__device__ __nv_bfloat16 g_attlo[S_ * D_];
__device__ __nv_bfloat16 g_ffhi [S_ * FF_];
__device__ __nv_bfloat16 g_fflo [S_ * FF_];

// ---------------- helpers ----------------
__device__ __forceinline__ u32 smem_u32(const void* p) {
    return (u32)__cvta_generic_to_shared(p);
}
__device__ __forceinline__ void cpasync16(u32 dst, const void* src) {
    asm volatile("cp.async.cg.shared.global [%0], [%1], 16;" :: "r"(dst), "l"(src));
}
__device__ __forceinline__ void ldm_x4(u32& r0, u32& r1, u32& r2, u32& r3, u32 a) {
    asm volatile("ldmatrix.sync.aligned.m8n8.x4.shared.b16 {%0,%1,%2,%3}, [%4];"
        : "=r"(r0), "=r"(r1), "=r"(r2), "=r"(r3) : "r"(a));
}
__device__ __forceinline__ void mma16816(float* d, const u32* a, const u32* b) {
    asm volatile("mma.sync.aligned.m16n8k16.row.col.f32.bf16.bf16.f32 "
        "{%0,%1,%2,%3}, {%4,%5,%6,%7}, {%8,%9}, {%0,%1,%2,%3};"
        : "+f"(d[0]), "+f"(d[1]), "+f"(d[2]), "+f"(d[3])
        : "r"(a[0]), "r"(a[1]), "r"(a[2]), "r"(a[3]), "r"(b[0]), "r"(b[1]));
}
__device__ __forceinline__ u32 sw_off(int r, int c) {
    return (u32)(r * 64 + ((c ^ ((r >> 1) & 3)) << 4));
}
__device__ __forceinline__ void split_store(float v, __nv_bfloat16* hi, __nv_bfloat16* lo, size_t i) {
    __nv_bfloat16 h = __float2bfloat16(v);
    hi[i] = h;
    lo[i] = __float2bfloat16(v - __bfloat162float(h));
}

// compile-time weight / scale / activation selectors
template<int W> __device__ __forceinline__ __nv_bfloat16* qsel() {
    if (W == 0) return g_qw;
    if (W == 1) return g_qwo;
    if (W == 2) return g_qwfc;
    if (W == 3) return g_qwpr;
    return g_qlm;
}
template<int W> __device__ __forceinline__ float* scsel() {
    if (W == 0) return g_sqkv;
    if (W == 1) return g_swo;
    if (W == 2) return g_swfc;
    if (W == 3) return g_swpr;
    return g_slm;
}
template<int A> __device__ __forceinline__ const __nv_bfloat16* ahisel() {
    if (A == 0) return g_hhi;
    if (A == 1) return g_atthi;
    return g_ffhi;
}
template<int A> __device__ __forceinline__ const __nv_bfloat16* alosel() {
    if (A == 0) return g_hlo;
    if (A == 1) return g_attlo;
    return g_fflo;
}

// ---------------- fake-quant: per-row top-2 abs -> clip -> q (bf16 int) + scale ----------------
// out_row = (blk / rpl) * ld + off + (blk % rpl)
template<int WSEL>
__global__ void quant_kernel(const float* __restrict__ W, int n, int rpl, int ld, int off)
{
    int blk = blockIdx.x;
    int l = blk / rpl, r = blk % rpl;
    int out_row = l * ld + off + r;
    const float* w = W + (size_t)blk * n;
    __nv_bfloat16* qb = qsel<WSEL>() + (size_t)out_row * n;
    int tid = threadIdx.x;

    float m1 = 0.f, m2 = 0.f;
    for (int i = tid; i < n; i += 256) {
        float a = fabsf(w[i]);
        if (a > m1) { m2 = m1; m1 = a; }
        else if (a > m2) { m2 = a; }
    }
    __shared__ float s1[256], s2[256];
    s1[tid] = m1; s2[tid] = m2;
    __syncthreads();
    for (int o = 128; o; o >>= 1) {
        if (tid < o) {
            float a1 = s1[tid], a2 = s2[tid];
            float b1 = s1[tid + o], b2 = s2[tid + o];
            s1[tid] = fmaxf(a1, b1);
            s2[tid] = fmaxf(fminf(a1, b1), fmaxf(a2, b2));
        }
        __syncthreads();
    }
    __shared__ float sh_clip, sh_scale;
    if (tid == 0) {
        float M1 = s1[0], M2 = s2[0];
        float idxf = 0.9999984f * (float)(n - 1);
        float frac = idxf - (float)(n - 2);
        float clip = M2 * (1.0f - frac) + M1 * frac;
        float scale = fmaxf(__fdiv_rn(clip, 127.0f), 1.0f / 127.0f);
        sh_clip = clip;
        sh_scale = scale;
        scsel<WSEL>()[out_row] = __half2float(__float2half_rn(scale));
    }
    __syncthreads();
    float clip = sh_clip, scale = sh_scale;
    for (int i = tid; i < n; i += 256) {
        float v = w[i];
        float c = fminf(fmaxf(v, -clip), clip);
        float q = rintf(__fdiv_rn(c, scale));
        q = fminf(fmaxf(q, -127.f), 127.f);
        qb[i] = __float2bfloat16(q);
    }
}

// ---------------- embedding ----------------
__global__ void embed_kernel(const int* __restrict__ idx, const float* __restrict__ emb)
{
    int i = blockIdx.x * blockDim.x + threadIdx.x;
    int s = i >> 10, d = i & 1023;
    g_x[i] = emb[(size_t)idx[s] * D_ + d];
}

// ---------------- rmsnorm of g_x -> g_hhi / g_hlo ----------------
__global__ void rmsnorm_split_kernel()
{
    int row = blockIdx.x;
    const float* xr = g_x + (size_t)row * D_;
    int tid = threadIdx.x;
    float ss = 0.f;
    for (int i = tid; i < D_; i += 256) { float v = xr[i]; ss += v * v; }
    __shared__ float sh[256];
    sh[tid] = ss; __syncthreads();
    for (int o = 128; o; o >>= 1) {
        if (tid < o) sh[tid] += sh[tid + o];
        __syncthreads();
    }
    float r = rsqrtf(sh[0] / (float)D_ + EPS_);
    for (int i = tid; i < D_; i += 256) {
        split_store(xr[i] * r, g_hhi, g_hlo, (size_t)row * D_ + i);
    }
}

// ---------------- per-head RMS + RoPE + gain on g_qkv ----------------
__global__ void qkpost_kernel(const float* __restrict__ gain, int nh, int off, int use_gain)
{
    int warp = (blockIdx.x * blockDim.x + threadIdx.x) >> 5;
    int lane = threadIdx.x & 31;
    int s = warp / nh, h = warp % nh;
    if (s >= S_) return;
    float* base = g_qkv + (size_t)s * QKVD_ + off + h * HD_;
    float e0 = base[lane], e1 = base[lane + 32];
    float ss = e0 * e0 + e1 * e1;
    #pragma unroll
    for (int o = 16; o; o >>= 1) ss += __shfl_xor_sync(0xffffffffu, ss, o);
    float r = rsqrtf(ss * (1.f / 64.f) + EPS_);
    e0 *= r; e1 *= r;
    float inv = (float)exp(-((double)lane / 32.0) * 9.210340371976184);
    float f = (float)s * inv;
    float c  = (float)cos((double)f);
    float sn = (float)sin((double)f);
    float o0 =  e0 * c + e1 * sn;
    float o1 = -e0 * sn + e1 * c;
    float g = use_gain ? gain[h] : 1.0f;
    base[lane]      = o0 * g;
    base[lane + 32] = o1 * g;
}

// ---------------- attention scores ----------------
__global__ void scores_kernel()
{
    int bi = blockIdx.y, bj = blockIdx.x, h = blockIdx.z;
    if (bj > bi) return;
    int kvh = h >> 2;
    __shared__ float qs[16][65];
    __shared__ float ks[16][65];
    int tx = threadIdx.x, ty = threadIdx.y;
    int tid = ty * 16 + tx;
    {
        int r = tid >> 4, c4 = (tid & 15) * 4;
        const float4 qv = *(const float4*)(g_qkv + (size_t)(bi * 16 + r) * QKVD_ + h * HD_ + c4);
        const float4 kv = *(const float4*)(g_qkv + (size_t)(bj * 16 + r) * QKVD_ + 1024 + kvh * HD_ + c4);
        qs[r][c4] = qv.x; qs[r][c4+1] = qv.y; qs[r][c4+2] = qv.z; qs[r][c4+3] = qv.w;
        ks[r][c4] = kv.x; ks[r][c4+1] = kv.y; ks[r][c4+2] = kv.z; ks[r][c4+3] = kv.w;
    }
    __syncthreads();
    int gi = bi * 16 + ty, gj = bj * 16 + tx;
    if (gj > gi) return;
    float acc = 0.f;
    #pragma unroll
    for (int d = 0; d < 64; d++) acc += qs[ty][d] * ks[tx][d];
    g_sc[((size_t)h * S_ + gi) * S_ + gj] = acc * 0.125f;
}

// ---------------- causal softmax ----------------
__global__ void softmax_kernel()
{
    int i = blockIdx.x, h = blockIdx.y;
    float* row = g_sc + ((size_t)h * S_ + i) * S_;
    int len = i + 1;
    int tid = threadIdx.x;
    __shared__ float sh[256];
    float m = -FLT_MAX;
    for (int j = tid; j < len; j += 256) m = fmaxf(m, row[j]);
    sh[tid] = m; __syncthreads();
    for (int o = 128; o; o >>= 1) {
        if (tid < o) sh[tid] = fmaxf(sh[tid], sh[tid + o]);
        __syncthreads();
    }
    float M = sh[0];
    __syncthreads();
    float sum = 0.f;
    for (int j = tid; j < len; j += 256) {
        float e = expf(row[j] - M);
        row[j] = e;
        sum += e;
    }
    sh[tid] = sum; __syncthreads();
    for (int o = 128; o; o >>= 1) {
        if (tid < o) sh[tid] += sh[tid + o];
        __syncthreads();
    }
    float inv = 1.0f / sh[0];
    for (int j = tid; j < S_; j += 256)
        row[j] = (j < len) ? row[j] * inv : 0.0f;
}

// ---------------- AV -> g_atthi / g_attlo ----------------
__global__ void av_kernel()
{
    int h = blockIdx.y, kvh = h >> 2;
    int tx = threadIdx.x;
    int ty = threadIdx.y;
    int tid = ty * 64 + tx;
    int i = blockIdx.x * 4 + ty;
    __shared__ float vs[64][65];
    __shared__ float ps[4][64];
    int ntiles = (blockIdx.x * 4 + 3) / 64 + 1;
    float acc = 0.f;
    const float* prow = g_sc + ((size_t)h * S_ + i) * S_;
    for (int jt = 0; jt < ntiles; jt++) {
        #pragma unroll
        for (int t = 0; t < 16; t++) {
            int id2 = tid + t * 256;
            int jj = id2 >> 6, d = id2 & 63;
            vs[jj][d] = g_qkv[(size_t)(jt * 64 + jj) * QKVD_ + 1280 + kvh * HD_ + d];
        }
        ps[ty][tx] = prow[jt * 64 + tx];
        __syncthreads();
        #pragma unroll
        for (int jj = 0; jj < 64; jj++) acc += ps[ty][jj] * vs[jj][tx];
        __syncthreads();
    }
    split_store(acc, g_atthi, g_attlo, (size_t)i * D_ + h * HD_ + tx);
}

// ---------------- tensor-core GEMM ----------------
// EPI: 0 = write g_qkv, 1 = residual add into g_x, 2 = relu^2 split into g_ff, 3 = write Cout
template<int BM, int BN>
__device__ __forceinline__ void load_stage(
    const __nv_bfloat16* Ahi, const __nv_bfloat16* Alo, const __nv_bfloat16* Bq,
    u32 sA_base, u32 sB_base, int st, int k0,
    int row0, int col0, int K, int tid)
{
    for (int id = tid; id < BM * 4; id += 256) {
        int r = id >> 2, c = id & 3;
        u32 so = sw_off(r, c);
        size_t gidx = (size_t)(row0 + r) * K + k0 + c * 8;
        cpasync16(sA_base + (u32)(st * 2 + 0) * (BM * 64) + so, Ahi + gidx);
        cpasync16(sA_base + (u32)(st * 2 + 1) * (BM * 64) + so, Alo + gidx);
    }
    for (int id = tid; id < BN * 4; id += 256) {
        int r = id >> 2, c = id & 3;
        cpasync16(sB_base + (u32)st * (BN * 64) + sw_off(r, c),
                  Bq + (size_t)(col0 + r) * K + k0 + c * 8);
    }
    asm volatile("cp.async.commit_group;");
}

template<int BM, int BN, int WM, int WN, int EPI, int WSEL, int ASEL>
__global__ __launch_bounds__(256, 1)
void qgemm_kernel(float* __restrict__ Cout, int layer, int N, int K, int ldc)
{
    constexpr int TM = BM / WM, TN = BN / WN;
    constexpr int MI = TM / 16, NI = TN / 8;

    __shared__ __align__(16) __nv_bfloat16 sA[2][2][BM * 32];
    __shared__ __align__(16) __nv_bfloat16 sB[2][BN * 32];

    int tid = threadIdx.x, lane = tid & 31, wid = tid >> 5;
    int wm = wid % WM, wn = wid / WM;
    int row0 = blockIdx.y * BM, col0 = blockIdx.x * BN;

    const __nv_bfloat16* Ahi = ahisel<ASEL>();
    const __nv_bfloat16* Alo = alosel<ASEL>();
    const __nv_bfloat16* Bq = qsel<WSEL>() + (size_t)layer * N * K;
    const float* Sc = scsel<WSEL>() + (size_t)layer * N;

    u32 sA_base = smem_u32(&sA[0][0][0]);
    u32 sB_base = smem_u32(&sB[0][0]);

    float acc[MI][NI][4];
    #pragma unroll
    for (int mi = 0; mi < MI; mi++) {
        #pragma unroll
        for (int ni = 0; ni < NI; ni++) {
            acc[mi][ni][0] = 0.f; acc[mi][ni][1] = 0.f;
            acc[mi][ni][2] = 0.f; acc[mi][ni][3] = 0.f;
        }
    }

    int nIter = K >> 5;
    load_stage<BM, BN>(Ahi, Alo, Bq, sA_base, sB_base, 0, 0, row0, col0, K, tid);

    for (int it = 0; it < nIter; it++) {
        if (it + 1 < nIter) {
            load_stage<BM, BN>(Ahi, Alo, Bq, sA_base, sB_base, (it + 1) & 1, (it + 1) << 5,
                               row0, col0, K, tid);
            asm volatile("cp.async.wait_group 1;");
        } else {
            asm volatile("cp.async.wait_group 0;");
        }
        __syncthreads();

        int st = it & 1;
        #pragma unroll
        for (int kc = 0; kc < 2; kc++) {
            u32 ah[MI][4], al[MI][4];
            #pragma unroll
            for (int mi = 0; mi < MI; mi++) {
                int lr = wm * TM + mi * 16 + (lane & 15);
                int ch = kc * 2 + (lane >> 4);
                ldm_x4(ah[mi][0], ah[mi][1], ah[mi][2], ah[mi][3],
                       sA_base + (u32)(st * 2 + 0) * (BM * 64) + sw_off(lr, ch));
                ldm_x4(al[mi][0], al[mi][1], al[mi][2], al[mi][3],
                       sA_base + (u32)(st * 2 + 1) * (BM * 64) + sw_off(lr, ch));
            }
            u32 bb[NI][2];
            #pragma unroll
            for (int nj = 0; nj < NI / 2; nj++) {
                int g = lane >> 3;
                int lr = wn * TN + nj * 16 + (((g >> 1) & 1) << 3) + (lane & 7);
                int ch = kc * 2 + (g & 1);
                u32 r0, r1, r2, r3;
                ldm_x4(r0, r1, r2, r3, sB_base + (u32)st * (BN * 64) + sw_off(lr, ch));
                bb[nj * 2][0] = r0; bb[nj * 2][1] = r1;
                bb[nj * 2 + 1][0] = r2; bb[nj * 2 + 1][1] = r3;
            }
            #pragma unroll
            for (int mi = 0; mi < MI; mi++) {
                #pragma unroll
                for (int ni = 0; ni < NI; ni++) {
                    mma16816(acc[mi][ni], ah[mi], bb[ni]);
                    mma16816(acc[mi][ni], al[mi], bb[ni]);
                }
            }
        }
        __syncthreads();
    }

    #pragma unroll
    for (int mi = 0; mi < MI; mi++) {
        #pragma unroll
        for (int ni = 0; ni < NI; ni++) {
            int gr0 = row0 + wm * TM + mi * 16 + (lane >> 2);
            int gc  = col0 + wn * TN + ni * 8 + ((lane & 3) << 1);
            #pragma unroll
            for (int half = 0; half < 2; half++) {
                int gr = gr0 + half * 8;
                #pragma unroll
                for (int e = 0; e < 2; e++) {
                    int c = gc + e;
                    if (c >= N) continue;
                    float v = acc[mi][ni][half * 2 + e] * Sc[c];
                    if (EPI == 0) {
                        g_qkv[(size_t)gr * QKVD_ + c] = v;
                    } else if (EPI == 1) {
                        g_x[(size_t)gr * D_ + c] += v;
                    } else if (EPI == 2) {
                        float t = fmaxf(v, 0.f);
                        split_store(t * t, g_ffhi, g_fflo, (size_t)gr * FF_ + c);
                    } else {
                        Cout[(size_t)gr * ldc + c] = v;
                    }
                }
            }
        }
    }
}

// ---------------- host orchestration ----------------
extern "C" void kernel_launch(void* const* d_in, const int* in_sizes, int n_in,
                              void* d_out, int out_size)
{
    (void)in_sizes; (void)n_in; (void)out_size;
    const int*   idx = (const int*)  d_in[0];
    const float* emb = (const float*)d_in[1];
    const float* wq  = (const float*)d_in[2];
    const float* wk  = (const float*)d_in[3];
    const float* wv  = (const float*)d_in[4];
    const float* wo  = (const float*)d_in[5];
    const float* qg  = (const float*)d_in[6];
    const float* wfc = (const float*)d_in[7];
    const float* wpr = (const float*)d_in[8];
    const float* lm  = (const float*)d_in[9];
    float* out = (float*)d_out;

    // 1) fake-quant all weights (qkv fused into [1536,1024] per layer)
    quant_kernel<0><<<L_ * D_,   256>>>(wq,  D_,  D_,   QKVD_, 0);
    quant_kernel<0><<<L_ * KVD_, 256>>>(wk,  D_,  KVD_, QKVD_, 1024);
    quant_kernel<0><<<L_ * KVD_, 256>>>(wv,  D_,  KVD_, QKVD_, 1280);
    quant_kernel<1><<<L_ * D_,   256>>>(wo,  D_,  L_ * D_,  0, 0);
    quant_kernel<2><<<L_ * FF_,  256>>>(wfc, D_,  L_ * FF_, 0, 0);
    quant_kernel<3><<<L_ * D_,   256>>>(wpr, FF_, L_ * D_,  0, 0);
    quant_kernel<4><<<V_,        256>>>(lm,  D_,  V_,       0, 0);

    // 2) embedding
    embed_kernel<<<(S_ * D_) / 256, 256>>>(idx, emb);

    // 3) transformer blocks
    for (int l = 0; l < L_; l++) {
        rmsnorm_split_kernel<<<S_, 256>>>();

        // fused QKV
        qgemm_kernel<128, 64, 4, 2, 0, 0, 0><<<dim3(QKVD_ / 64, S_ / 128), 256>>>(
            nullptr, l, QKVD_, D_, QKVD_);

        qkpost_kernel<<<(S_ * H_)  / 4, 128>>>(qg + l * H_, H_,  0,    1);
        qkpost_kernel<<<(S_ * KV_) / 4, 128>>>(nullptr,     KV_, 1024, 0);

        scores_kernel<<<dim3(S_ / 16, S_ / 16, H_), dim3(16, 16)>>>();
        softmax_kernel<<<dim3(S_, H_), 256>>>();
        av_kernel<<<dim3(S_ / 4, H_), dim3(64, 4)>>>();

        // out proj + residual
        qgemm_kernel<128, 64, 4, 2, 1, 1, 1><<<dim3(D_ / 64, S_ / 128), 256>>>(
            nullptr, l, D_, D_, D_);

        rmsnorm_split_kernel<<<S_, 256>>>();

        // fc + relu^2 split
        qgemm_kernel<128, 128, 2, 4, 2, 2, 0><<<dim3(FF_ / 128, S_ / 128), 256>>>(
            nullptr, l, FF_, D_, FF_);

        // proj + residual
        qgemm_kernel<128, 64, 4, 2, 1, 3, 2><<<dim3(D_ / 64, S_ / 128), 256>>>(
            nullptr, l, D_, FF_, D_);
    }

    // 4) final norm + lm_head
    rmsnorm_split_kernel<<<S_, 256>>>();
    qgemm_kernel<128, 128, 2, 4, 3, 4, 0><<<dim3(VPAD_ / 128, S_ / 128), 256>>>(
        out, 0, V_, D_, V_);
}

// round 6
// speedup vs baseline: 5.7522x; 1.5106x over previous
#include <cuda_runtime.h>
#include <cuda_fp16.h>
#include <cuda_bf16.h>
#include <stdint.h>
#include <cstdint>
#include <math.h>
#include <float.h>

typedef unsigned int u32;

#define S_   1024
#define D_   1024
#define H_   16
#define KV_  4
#define HD_  64
#define KVD_ 256
#define FF_  4096
#define L_   8
#define V_   50257
#define VPAD_ 50304
#define QKVD_ 1536
#define EPS_ 1.1920928955078125e-07f

// ---------------- device globals ----------------
__device__ __nv_bfloat16 g_qw  [L_ * QKVD_ * D_];
__device__ __nv_bfloat16 g_qwo [L_ * D_   * D_ ];
__device__ __nv_bfloat16 g_qwfc[L_ * FF_  * D_ ];
__device__ __nv_bfloat16 g_qwpr[L_ * D_   * FF_];
__device__ __nv_bfloat16 g_qlm [(size_t)VPAD_ * D_];
__device__ float g_sqkv[L_ * QKVD_];
__device__ float g_swo [L_ * D_ ];
__device__ float g_swfc[L_ * FF_];
__device__ float g_swpr[L_ * D_ ];
__device__ float g_slm [VPAD_];

__device__ float g_x  [S_ * D_ ];
__device__ __nv_bfloat16 g_hhi[S_ * D_ ];
__device__ __nv_bfloat16 g_hlo[S_ * D_ ];
__device__ float g_qkv[S_ * QKVD_];
__device__ float g_sc [(size_t)H_ * S_ * S_];
__device__ __nv_bfloat16 g_atthi[S_ * D_];
__device__ __nv_bfloat16 g_attlo[S_ * D_];
__device__ __nv_bfloat16 g_ffhi [S_ * FF_];
__device__ __nv_bfloat16 g_fflo [S_ * FF_];

// attention tensor-core operands
__device__ __nv_bfloat16 g_qhi [S_ * D_ ];
__device__ __nv_bfloat16 g_qlo [S_ * D_ ];
__device__ __nv_bfloat16 g_khi [S_ * KVD_];
__device__ __nv_bfloat16 g_klo [S_ * KVD_];
__device__ __nv_bfloat16 g_vthi[KVD_ * S_];     // V^T: [kvh*64+d][s]
__device__ __nv_bfloat16 g_vtlo[KVD_ * S_];
__device__ __nv_bfloat16 g_phi [(size_t)H_ * S_ * S_];
__device__ __nv_bfloat16 g_plo [(size_t)H_ * S_ * S_];

// ---------------- helpers ----------------
__device__ __forceinline__ u32 smem_u32(const void* p) {
    return (u32)__cvta_generic_to_shared(p);
}
__device__ __forceinline__ void cpasync16(u32 dst, const void* src) {
    asm volatile("cp.async.cg.shared.global [%0], [%1], 16;" :: "r"(dst), "l"(src));
}
__device__ __forceinline__ void ldm_x4(u32& r0, u32& r1, u32& r2, u32& r3, u32 a) {
    asm volatile("ldmatrix.sync.aligned.m8n8.x4.shared.b16 {%0,%1,%2,%3}, [%4];"
        : "=r"(r0), "=r"(r1), "=r"(r2), "=r"(r3) : "r"(a));
}
__device__ __forceinline__ void mma16816(float* d, const u32* a, const u32* b) {
    asm volatile("mma.sync.aligned.m16n8k16.row.col.f32.bf16.bf16.f32 "
        "{%0,%1,%2,%3}, {%4,%5,%6,%7}, {%8,%9}, {%0,%1,%2,%3};"
        : "+f"(d[0]), "+f"(d[1]), "+f"(d[2]), "+f"(d[3])
        : "r"(a[0]), "r"(a[1]), "r"(a[2]), "r"(a[3]), "r"(b[0]), "r"(b[1]));
}
__device__ __forceinline__ u32 sw_off(int r, int c) {
    return (u32)(r * 64 + ((c ^ ((r >> 1) & 3)) << 4));
}
__device__ __forceinline__ void split_store(float v, __nv_bfloat16* hi, __nv_bfloat16* lo, size_t i) {
    __nv_bfloat16 h = __float2bfloat16(v);
    hi[i] = h;
    lo[i] = __float2bfloat16(v - __bfloat162float(h));
}

template<int W> __device__ __forceinline__ __nv_bfloat16* qsel() {
    if (W == 0) return g_qw;
    if (W == 1) return g_qwo;
    if (W == 2) return g_qwfc;
    if (W == 3) return g_qwpr;
    return g_qlm;
}
template<int W> __device__ __forceinline__ float* scsel() {
    if (W == 0) return g_sqkv;
    if (W == 1) return g_swo;
    if (W == 2) return g_swfc;
    if (W == 3) return g_swpr;
    return g_slm;
}
template<int A> __device__ __forceinline__ const __nv_bfloat16* ahisel() {
    if (A == 0) return g_hhi;
    if (A == 1) return g_atthi;
    return g_ffhi;
}
template<int A> __device__ __forceinline__ const __nv_bfloat16* alosel() {
    if (A == 0) return g_hlo;
    if (A == 1) return g_attlo;
    return g_fflo;
}

// ---------------- fake-quant ----------------
template<int WSEL>
__global__ void quant_kernel(const float* __restrict__ W, int n, int rpl, int ld, int off)
{
    int blk = blockIdx.x;
    int l = blk / rpl, r = blk % rpl;
    int out_row = l * ld + off + r;
    const float* w = W + (size_t)blk * n;
    __nv_bfloat16* qb = qsel<WSEL>() + (size_t)out_row * n;
    int tid = threadIdx.x;

    float m1 = 0.f, m2 = 0.f;
    for (int i = tid; i < n; i += 256) {
        float a = fabsf(w[i]);
        if (a > m1) { m2 = m1; m1 = a; }
        else if (a > m2) { m2 = a; }
    }
    __shared__ float s1[256], s2[256];
    s1[tid] = m1; s2[tid] = m2;
    __syncthreads();
    for (int o = 128; o; o >>= 1) {
        if (tid < o) {
            float a1 = s1[tid], a2 = s2[tid];
            float b1 = s1[tid + o], b2 = s2[tid + o];
            s1[tid] = fmaxf(a1, b1);
            s2[tid] = fmaxf(fminf(a1, b1), fmaxf(a2, b2));
        }
        __syncthreads();
    }
    __shared__ float sh_clip, sh_scale;
    if (tid == 0) {
        float M1 = s1[0], M2 = s2[0];
        float idxf = 0.9999984f * (float)(n - 1);
        float frac = idxf - (float)(n - 2);
        float clip = M2 * (1.0f - frac) + M1 * frac;
        float scale = fmaxf(__fdiv_rn(clip, 127.0f), 1.0f / 127.0f);
        sh_clip = clip;
        sh_scale = scale;
        scsel<WSEL>()[out_row] = __half2float(__float2half_rn(scale));
    }
    __syncthreads();
    float clip = sh_clip, scale = sh_scale;
    for (int i = tid; i < n; i += 256) {
        float v = w[i];
        float c = fminf(fmaxf(v, -clip), clip);
        float q = rintf(__fdiv_rn(c, scale));
        q = fminf(fmaxf(q, -127.f), 127.f);
        qb[i] = __float2bfloat16(q);
    }
}

// ---------------- embedding ----------------
__global__ void embed_kernel(const int* __restrict__ idx, const float* __restrict__ emb)
{
    int i = blockIdx.x * blockDim.x + threadIdx.x;
    int s = i >> 10, d = i & 1023;
    g_x[i] = emb[(size_t)idx[s] * D_ + d];
}

// ---------------- rmsnorm of g_x -> g_hhi / g_hlo ----------------
__global__ void rmsnorm_split_kernel()
{
    int row = blockIdx.x;
    const float* xr = g_x + (size_t)row * D_;
    int tid = threadIdx.x;
    float ss = 0.f;
    for (int i = tid; i < D_; i += 256) { float v = xr[i]; ss += v * v; }
    __shared__ float sh[256];
    sh[tid] = ss; __syncthreads();
    for (int o = 128; o; o >>= 1) {
        if (tid < o) sh[tid] += sh[tid + o];
        __syncthreads();
    }
    float r = rsqrtf(sh[0] / (float)D_ + EPS_);
    for (int i = tid; i < D_; i += 256) {
        split_store(xr[i] * r, g_hhi, g_hlo, (size_t)row * D_ + i);
    }
}

// ---------------- per-head RMS + RoPE + gain, writes bf16 hi/lo q or k ----------------
__global__ void qkpost_kernel(const float* __restrict__ gain, int nh, int off, int isq)
{
    int warp = (blockIdx.x * blockDim.x + threadIdx.x) >> 5;
    int lane = threadIdx.x & 31;
    int s = warp / nh, h = warp % nh;
    if (s >= S_) return;
    const float* base = g_qkv + (size_t)s * QKVD_ + off + h * HD_;
    float e0 = base[lane], e1 = base[lane + 32];
    float ss = e0 * e0 + e1 * e1;
    #pragma unroll
    for (int o = 16; o; o >>= 1) ss += __shfl_xor_sync(0xffffffffu, ss, o);
    float r = rsqrtf(ss * (1.f / 64.f) + EPS_);
    e0 *= r; e1 *= r;
    float inv = (float)exp(-((double)lane / 32.0) * 9.210340371976184);
    float f = (float)s * inv;
    float c  = (float)cos((double)f);
    float sn = (float)sin((double)f);
    float o0 =  e0 * c + e1 * sn;
    float o1 = -e0 * sn + e1 * c;
    if (isq) {
        float g = gain[h];
        split_store(o0 * g, g_qhi, g_qlo, (size_t)s * D_ + h * HD_ + lane);
        split_store(o1 * g, g_qhi, g_qlo, (size_t)s * D_ + h * HD_ + lane + 32);
    } else {
        split_store(o0, g_khi, g_klo, (size_t)s * KVD_ + h * HD_ + lane);
        split_store(o1, g_khi, g_klo, (size_t)s * KVD_ + h * HD_ + lane + 32);
    }
}

// ---------------- V transpose: g_qkv v-region [s][c] -> vt[c][s] hi/lo ----------------
__global__ void vtrans_kernel()
{
    __shared__ float t[32][33];
    int s0 = blockIdx.x * 32, c0 = blockIdx.y * 32;
    int tx = threadIdx.x, ty = threadIdx.y;   // 32 x 8
    #pragma unroll
    for (int k = 0; k < 32; k += 8)
        t[ty + k][tx] = g_qkv[(size_t)(s0 + ty + k) * QKVD_ + 1280 + c0 + tx];
    __syncthreads();
    #pragma unroll
    for (int k = 0; k < 32; k += 8) {
        float v = t[tx][ty + k];               // = V[s0+tx][c0+ty+k]
        split_store(v, g_vthi, g_vtlo, (size_t)(c0 + ty + k) * S_ + s0 + tx);
    }
}

// ---------------- tensor-core scores: g_sc[h][i][j] = (Q K^T)/8, causal ----------------
__global__ __launch_bounds__(128, 1) void tc_scores_kernel()
{
    int bi = blockIdx.y, bj = blockIdx.x, h = blockIdx.z;
    if (bj > bi) return;
    int kvh = h >> 2;

    __shared__ __align__(16) __nv_bfloat16 sQ[2][2][64 * 32];
    __shared__ __align__(16) __nv_bfloat16 sK[2][2][64 * 32];

    int tid = threadIdx.x, lane = tid & 31, wid = tid >> 5;
    int wm = wid & 1, wn = wid >> 1;      // 2x2 warps, warp tile 32x32
    u32 qb = smem_u32(&sQ[0][0][0]);
    u32 kb = smem_u32(&sK[0][0][0]);

    #pragma unroll
    for (int st = 0; st < 2; st++) {
        for (int id = tid; id < 64 * 4; id += 128) {
            int r = id >> 2, c = id & 3;
            u32 so = sw_off(r, c);
            size_t gq = (size_t)(bi * 64 + r) * D_ + h * HD_ + st * 32 + c * 8;
            cpasync16(qb + (u32)(st * 2 + 0) * 4096 + so, g_qhi + gq);
            cpasync16(qb + (u32)(st * 2 + 1) * 4096 + so, g_qlo + gq);
            size_t gk = (size_t)(bj * 64 + r) * KVD_ + kvh * HD_ + st * 32 + c * 8;
            cpasync16(kb + (u32)(st * 2 + 0) * 4096 + so, g_khi + gk);
            cpasync16(kb + (u32)(st * 2 + 1) * 4096 + so, g_klo + gk);
        }
    }
    asm volatile("cp.async.commit_group;");
    asm volatile("cp.async.wait_group 0;");
    __syncthreads();

    float acc[2][4][4];
    #pragma unroll
    for (int mi = 0; mi < 2; mi++)
        #pragma unroll
        for (int ni = 0; ni < 4; ni++) {
            acc[mi][ni][0] = 0.f; acc[mi][ni][1] = 0.f;
            acc[mi][ni][2] = 0.f; acc[mi][ni][3] = 0.f;
        }

    #pragma unroll
    for (int st = 0; st < 2; st++) {
        #pragma unroll
        for (int kc = 0; kc < 2; kc++) {
            u32 ah[2][4], al[2][4];
            #pragma unroll
            for (int mi = 0; mi < 2; mi++) {
                int lr = wm * 32 + mi * 16 + (lane & 15);
                int ch = kc * 2 + (lane >> 4);
                ldm_x4(ah[mi][0], ah[mi][1], ah[mi][2], ah[mi][3],
                       qb + (u32)(st * 2 + 0) * 4096 + sw_off(lr, ch));
                ldm_x4(al[mi][0], al[mi][1], al[mi][2], al[mi][3],
                       qb + (u32)(st * 2 + 1) * 4096 + sw_off(lr, ch));
            }
            u32 bh[4][2], bl[4][2];
            #pragma unroll
            for (int nj = 0; nj < 2; nj++) {
                int g = lane >> 3;
                int lr = wn * 32 + nj * 16 + (((g >> 1) & 1) << 3) + (lane & 7);
                int ch = kc * 2 + (g & 1);
                u32 r0, r1, r2, r3;
                ldm_x4(r0, r1, r2, r3, kb + (u32)(st * 2 + 0) * 4096 + sw_off(lr, ch));
                bh[nj * 2][0] = r0; bh[nj * 2][1] = r1;
                bh[nj * 2 + 1][0] = r2; bh[nj * 2 + 1][1] = r3;
                ldm_x4(r0, r1, r2, r3, kb + (u32)(st * 2 + 1) * 4096 + sw_off(lr, ch));
                bl[nj * 2][0] = r0; bl[nj * 2][1] = r1;
                bl[nj * 2 + 1][0] = r2; bl[nj * 2 + 1][1] = r3;
            }
            #pragma unroll
            for (int mi = 0; mi < 2; mi++) {
                #pragma unroll
                for (int ni = 0; ni < 4; ni++) {
                    mma16816(acc[mi][ni], ah[mi], bh[ni]);
                    mma16816(acc[mi][ni], ah[mi], bl[ni]);
                    mma16816(acc[mi][ni], al[mi], bh[ni]);
                }
            }
        }
    }

    #pragma unroll
    for (int mi = 0; mi < 2; mi++) {
        #pragma unroll
        for (int ni = 0; ni < 4; ni++) {
            int gi0 = bi * 64 + wm * 32 + mi * 16 + (lane >> 2);
            int gj0 = bj * 64 + wn * 32 + ni * 8 + ((lane & 3) << 1);
            #pragma unroll
            for (int half = 0; half < 2; half++) {
                int gi = gi0 + half * 8;
                #pragma unroll
                for (int e = 0; e < 2; e++) {
                    int gj = gj0 + e;
                    if (gj <= gi)
                        g_sc[((size_t)h * S_ + gi) * S_ + gj] = acc[mi][ni][half * 2 + e] * 0.125f;
                }
            }
        }
    }
}

// ---------------- causal softmax: fp32 in, bf16 hi/lo out with tile zero-fill ----------------
__global__ void softmax_kernel()
{
    int i = blockIdx.x, h = blockIdx.y;
    const float* row = g_sc + ((size_t)h * S_ + i) * S_;
    __nv_bfloat16* phi = g_phi + ((size_t)h * S_ + i) * S_;
    __nv_bfloat16* plo = g_plo + ((size_t)h * S_ + i) * S_;
    int len = i + 1;
    int zlim = ((i >> 6) + 1) << 6;
    int tid = threadIdx.x;
    __shared__ float sh[256];
    float m = -FLT_MAX;
    for (int j = tid; j < len; j += 256) m = fmaxf(m, row[j]);
    sh[tid] = m; __syncthreads();
    for (int o = 128; o; o >>= 1) {
        if (tid < o) sh[tid] = fmaxf(sh[tid], sh[tid + o]);
        __syncthreads();
    }
    float M = sh[0];
    __syncthreads();
    float sum = 0.f;
    for (int j = tid; j < len; j += 256) sum += expf(row[j] - M);
    sh[tid] = sum; __syncthreads();
    for (int o = 128; o; o >>= 1) {
        if (tid < o) sh[tid] += sh[tid + o];
        __syncthreads();
    }
    float inv = 1.0f / sh[0];
    for (int j = tid; j < zlim; j += 256) {
        float p = (j < len) ? expf(row[j] - M) * inv : 0.0f;
        __nv_bfloat16 hb = __float2bfloat16(p);
        phi[j] = hb;
        plo[j] = __float2bfloat16(p - __bfloat162float(hb));
    }
}

// ---------------- tensor-core AV: att[i][h*64+d] = sum_j P[h,i,j] V[j,d] ----------------
__device__ __forceinline__ void av_load(int h, int kvh, int row0, int st, int k0,
                                        u32 pb, u32 vb, int tid)
{
    for (int id = tid; id < 64 * 4; id += 128) {
        int r = id >> 2, c = id & 3;
        u32 so = sw_off(r, c);
        size_t gp = ((size_t)h * S_ + row0 + r) * S_ + k0 + c * 8;
        cpasync16(pb + (u32)(st * 2 + 0) * 4096 + so, g_phi + gp);
        cpasync16(pb + (u32)(st * 2 + 1) * 4096 + so, g_plo + gp);
        size_t gv = (size_t)(kvh * 64 + r) * S_ + k0 + c * 8;
        cpasync16(vb + (u32)(st * 2 + 0) * 4096 + so, g_vthi + gv);
        cpasync16(vb + (u32)(st * 2 + 1) * 4096 + so, g_vtlo + gv);
    }
    asm volatile("cp.async.commit_group;");
}

__global__ __launch_bounds__(128, 1) void tc_av_kernel()
{
    int mt = blockIdx.x, h = blockIdx.y, kvh = h >> 2;
    int row0 = mt * 64;

    __shared__ __align__(16) __nv_bfloat16 sP[2][2][64 * 32];
    __shared__ __align__(16) __nv_bfloat16 sV[2][2][64 * 32];

    int tid = threadIdx.x, lane = tid & 31, wid = tid >> 5;
    int wm = wid & 1, wn = wid >> 1;
    u32 pb = smem_u32(&sP[0][0][0]);
    u32 vb = smem_u32(&sV[0][0][0]);

    float acc[2][4][4];
    #pragma unroll
    for (int mi = 0; mi < 2; mi++)
        #pragma unroll
        for (int ni = 0; ni < 4; ni++) {
            acc[mi][ni][0] = 0.f; acc[mi][ni][1] = 0.f;
            acc[mi][ni][2] = 0.f; acc[mi][ni][3] = 0.f;
        }

    int nIter = (row0 >> 5) + 2;
    av_load(h, kvh, row0, 0, 0, pb, vb, tid);

    for (int it = 0; it < nIter; it++) {
        if (it + 1 < nIter) {
            av_load(h, kvh, row0, (it + 1) & 1, (it + 1) << 5, pb, vb, tid);
            asm volatile("cp.async.wait_group 1;");
        } else {
            asm volatile("cp.async.wait_group 0;");
        }
        __syncthreads();

        int st = it & 1;
        #pragma unroll
        for (int kc = 0; kc < 2; kc++) {
            u32 ah[2][4], al[2][4];
            #pragma unroll
            for (int mi = 0; mi < 2; mi++) {
                int lr = wm * 32 + mi * 16 + (lane & 15);
                int ch = kc * 2 + (lane >> 4);
                ldm_x4(ah[mi][0], ah[mi][1], ah[mi][2], ah[mi][3],
                       pb + (u32)(st * 2 + 0) * 4096 + sw_off(lr, ch));
                ldm_x4(al[mi][0], al[mi][1], al[mi][2], al[mi][3],
                       pb + (u32)(st * 2 + 1) * 4096 + sw_off(lr, ch));
            }
            u32 bh[4][2], bl[4][2];
            #pragma unroll
            for (int nj = 0; nj < 2; nj++) {
                int g = lane >> 3;
                int lr = wn * 32 + nj * 16 + (((g >> 1) & 1) << 3) + (lane & 7);
                int ch = kc * 2 + (g & 1);
                u32 r0, r1, r2, r3;
                ldm_x4(r0, r1, r2, r3, vb + (u32)(st * 2 + 0) * 4096 + sw_off(lr, ch));
                bh[nj * 2][0] = r0; bh[nj * 2][1] = r1;
                bh[nj * 2 + 1][0] = r2; bh[nj * 2 + 1][1] = r3;
                ldm_x4(r0, r1, r2, r3, vb + (u32)(st * 2 + 1) * 4096 + sw_off(lr, ch));
                bl[nj * 2][0] = r0; bl[nj * 2][1] = r1;
                bl[nj * 2 + 1][0] = r2; bl[nj * 2 + 1][1] = r3;
            }
            #pragma unroll
            for (int mi = 0; mi < 2; mi++) {
                #pragma unroll
                for (int ni = 0; ni < 4; ni++) {
                    mma16816(acc[mi][ni], ah[mi], bh[ni]);
                    mma16816(acc[mi][ni], ah[mi], bl[ni]);
                    mma16816(acc[mi][ni], al[mi], bh[ni]);
                }
            }
        }
        __syncthreads();
    }

    #pragma unroll
    for (int mi = 0; mi < 2; mi++) {
        #pragma unroll
        for (int ni = 0; ni < 4; ni++) {
            int gi0 = row0 + wm * 32 + mi * 16 + (lane >> 2);
            int gd0 = wn * 32 + ni * 8 + ((lane & 3) << 1);
            #pragma unroll
            for (int half = 0; half < 2; half++) {
                int gi = gi0 + half * 8;
                #pragma unroll
                for (int e = 0; e < 2; e++) {
                    int gd = gd0 + e;
                    split_store(acc[mi][ni][half * 2 + e], g_atthi, g_attlo,
                                (size_t)gi * D_ + h * HD_ + gd);
                }
            }
        }
    }
}

// ---------------- tensor-core GEMM (weights) ----------------
// EPI: 0 = write g_qkv, 1 = residual add into g_x, 2 = relu^2 split into g_ff, 3 = write Cout
template<int BM, int BN>
__device__ __forceinline__ void load_stage(
    const __nv_bfloat16* Ahi, const __nv_bfloat16* Alo, const __nv_bfloat16* Bq,
    u32 sA_base, u32 sB_base, int st, int k0,
    int row0, int col0, int K, int tid)
{
    for (int id = tid; id < BM * 4; id += 256) {
        int r = id >> 2, c = id & 3;
        u32 so = sw_off(r, c);
        size_t gidx = (size_t)(row0 + r) * K + k0 + c * 8;
        cpasync16(sA_base + (u32)(st * 2 + 0) * (BM * 64) + so, Ahi + gidx);
        cpasync16(sA_base + (u32)(st * 2 + 1) * (BM * 64) + so, Alo + gidx);
    }
    for (int id = tid; id < BN * 4; id += 256) {
        int r = id >> 2, c = id & 3;
        cpasync16(sB_base + (u32)st * (BN * 64) + sw_off(r, c),
                  Bq + (size_t)(col0 + r) * K + k0 + c * 8);
    }
    asm volatile("cp.async.commit_group;");
}

template<int BM, int BN, int WM, int WN, int EPI, int WSEL, int ASEL>
__global__ __launch_bounds__(256, 1)
void qgemm_kernel(float* __restrict__ Cout, int layer, int N, int K, int ldc)
{
    constexpr int TM = BM / WM, TN = BN / WN;
    constexpr int MI = TM / 16, NI = TN / 8;

    __shared__ __align__(16) __nv_bfloat16 sA[2][2][BM * 32];
    __shared__ __align__(16) __nv_bfloat16 sB[2][BN * 32];

    int tid = threadIdx.x, lane = tid & 31, wid = tid >> 5;
    int wm = wid % WM, wn = wid / WM;
    int row0 = blockIdx.y * BM, col0 = blockIdx.x * BN;

    const __nv_bfloat16* Ahi = ahisel<ASEL>();
    const __nv_bfloat16* Alo = alosel<ASEL>();
    const __nv_bfloat16* Bq = qsel<WSEL>() + (size_t)layer * N * K;
    const float* Sc = scsel<WSEL>() + (size_t)layer * N;

    u32 sA_base = smem_u32(&sA[0][0][0]);
    u32 sB_base = smem_u32(&sB[0][0]);

    float acc[MI][NI][4];
    #pragma unroll
    for (int mi = 0; mi < MI; mi++) {
        #pragma unroll
        for (int ni = 0; ni < NI; ni++) {
            acc[mi][ni][0] = 0.f; acc[mi][ni][1] = 0.f;
            acc[mi][ni][2] = 0.f; acc[mi][ni][3] = 0.f;
        }
    }

    int nIter = K >> 5;
    load_stage<BM, BN>(Ahi, Alo, Bq, sA_base, sB_base, 0, 0, row0, col0, K, tid);

    for (int it = 0; it < nIter; it++) {
        if (it + 1 < nIter) {
            load_stage<BM, BN>(Ahi, Alo, Bq, sA_base, sB_base, (it + 1) & 1, (it + 1) << 5,
                               row0, col0, K, tid);
            asm volatile("cp.async.wait_group 1;");
        } else {
            asm volatile("cp.async.wait_group 0;");
        }
        __syncthreads();

        int st = it & 1;
        #pragma unroll
        for (int kc = 0; kc < 2; kc++) {
            u32 ah[MI][4], al[MI][4];
            #pragma unroll
            for (int mi = 0; mi < MI; mi++) {
                int lr = wm * TM + mi * 16 + (lane & 15);
                int ch = kc * 2 + (lane >> 4);
                ldm_x4(ah[mi][0], ah[mi][1], ah[mi][2], ah[mi][3],
                       sA_base + (u32)(st * 2 + 0) * (BM * 64) + sw_off(lr, ch));
                ldm_x4(al[mi][0], al[mi][1], al[mi][2], al[mi][3],
                       sA_base + (u32)(st * 2 + 1) * (BM * 64) + sw_off(lr, ch));
            }
            u32 bb[NI][2];
            #pragma unroll
            for (int nj = 0; nj < NI / 2; nj++) {
                int g = lane >> 3;
                int lr = wn * TN + nj * 16 + (((g >> 1) & 1) << 3) + (lane & 7);
                int ch = kc * 2 + (g & 1);
                u32 r0, r1, r2, r3;
                ldm_x4(r0, r1, r2, r3, sB_base + (u32)st * (BN * 64) + sw_off(lr, ch));
                bb[nj * 2][0] = r0; bb[nj * 2][1] = r1;
                bb[nj * 2 + 1][0] = r2; bb[nj * 2 + 1][1] = r3;
            }
            #pragma unroll
            for (int mi = 0; mi < MI; mi++) {
                #pragma unroll
                for (int ni = 0; ni < NI; ni++) {
                    mma16816(acc[mi][ni], ah[mi], bb[ni]);
                    mma16816(acc[mi][ni], al[mi], bb[ni]);
                }
            }
        }
        __syncthreads();
    }

    #pragma unroll
    for (int mi = 0; mi < MI; mi++) {
        #pragma unroll
        for (int ni = 0; ni < NI; ni++) {
            int gr0 = row0 + wm * TM + mi * 16 + (lane >> 2);
            int gc  = col0 + wn * TN + ni * 8 + ((lane & 3) << 1);
            #pragma unroll
            for (int half = 0; half < 2; half++) {
                int gr = gr0 + half * 8;
                #pragma unroll
                for (int e = 0; e < 2; e++) {
                    int c = gc + e;
                    if (c >= N) continue;
                    float v = acc[mi][ni][half * 2 + e] * Sc[c];
                    if (EPI == 0) {
                        g_qkv[(size_t)gr * QKVD_ + c] = v;
                    } else if (EPI == 1) {
                        g_x[(size_t)gr * D_ + c] += v;
                    } else if (EPI == 2) {
                        float t = fmaxf(v, 0.f);
                        split_store(t * t, g_ffhi, g_fflo, (size_t)gr * FF_ + c);
                    } else {
                        Cout[(size_t)gr * ldc + c] = v;
                    }
                }
            }
        }
    }
}

// ---------------- host orchestration ----------------
extern "C" void kernel_launch(void* const* d_in, const int* in_sizes, int n_in,
                              void* d_out, int out_size)
{
    (void)in_sizes; (void)n_in; (void)out_size;
    const int*   idx = (const int*)  d_in[0];
    const float* emb = (const float*)d_in[1];
    const float* wq  = (const float*)d_in[2];
    const float* wk  = (const float*)d_in[3];
    const float* wv  = (const float*)d_in[4];
    const float* wo  = (const float*)d_in[5];
    const float* qg  = (const float*)d_in[6];
    const float* wfc = (const float*)d_in[7];
    const float* wpr = (const float*)d_in[8];
    const float* lm  = (const float*)d_in[9];
    float* out = (float*)d_out;

    quant_kernel<0><<<L_ * D_,   256>>>(wq,  D_,  D_,   QKVD_, 0);
    quant_kernel<0><<<L_ * KVD_, 256>>>(wk,  D_,  KVD_, QKVD_, 1024);
    quant_kernel<0><<<L_ * KVD_, 256>>>(wv,  D_,  KVD_, QKVD_, 1280);
    quant_kernel<1><<<L_ * D_,   256>>>(wo,  D_,  L_ * D_,  0, 0);
    quant_kernel<2><<<L_ * FF_,  256>>>(wfc, D_,  L_ * FF_, 0, 0);
    quant_kernel<3><<<L_ * D_,   256>>>(wpr, FF_, L_ * D_,  0, 0);
    quant_kernel<4><<<V_,        256>>>(lm,  D_,  V_,       0, 0);

    embed_kernel<<<(S_ * D_) / 256, 256>>>(idx, emb);

    for (int l = 0; l < L_; l++) {
        rmsnorm_split_kernel<<<S_, 256>>>();

        qgemm_kernel<128, 64, 4, 2, 0, 0, 0><<<dim3(QKVD_ / 64, S_ / 128), 256>>>(
            nullptr, l, QKVD_, D_, QKVD_);

        qkpost_kernel<<<(S_ * H_)  / 4, 128>>>(qg + l * H_, H_,  0,    1);
        qkpost_kernel<<<(S_ * KV_) / 4, 128>>>(nullptr,     KV_, 1024, 0);
        vtrans_kernel<<<dim3(S_ / 32, KVD_ / 32), dim3(32, 8)>>>();

        tc_scores_kernel<<<dim3(16, 16, H_), 128>>>();
        softmax_kernel<<<dim3(S_, H_), 256>>>();
        tc_av_kernel<<<dim3(16, H_), 128>>>();

        qgemm_kernel<128, 64, 4, 2, 1, 1, 1><<<dim3(D_ / 64, S_ / 128), 256>>>(
            nullptr, l, D_, D_, D_);

        rmsnorm_split_kernel<<<S_, 256>>>();

        qgemm_kernel<128, 128, 2, 4, 2, 2, 0><<<dim3(FF_ / 128, S_ / 128), 256>>>(
            nullptr, l, FF_, D_, FF_);

        qgemm_kernel<128, 64, 4, 2, 1, 3, 2><<<dim3(D_ / 64, S_ / 128), 256>>>(
            nullptr, l, D_, FF_, D_);
    }

    rmsnorm_split_kernel<<<S_, 256>>>();
    qgemm_kernel<128, 128, 2, 4, 3, 4, 0><<<dim3(VPAD_ / 128, S_ / 128), 256>>>(
        out, 0, V_, D_, V_);
}

// round 8
// speedup vs baseline: 5.9407x; 1.0328x over previous
#include <cuda_runtime.h>
#include <cuda_fp16.h>
#include <cuda_bf16.h>
#include <stdint.h>
#include <cstdint>
#include <math.h>
#include <float.h>

typedef unsigned int u32;

#define S_   1024
#define D_   1024
#define H_   16
#define KV_  4
#define HD_  64
#define KVD_ 256
#define FF_  4096
#define L_   8
#define V_   50257
#define VPAD_ 50304
#define QKVD_ 1536
#define EPS_ 1.1920928955078125e-07f

// ---------------- device globals ----------------
__device__ __nv_bfloat16 g_qw  [L_ * QKVD_ * D_];
__device__ __nv_bfloat16 g_qwo [L_ * D_   * D_ ];
__device__ __nv_bfloat16 g_qwfc[L_ * FF_  * D_ ];
__device__ __nv_bfloat16 g_qwpr[L_ * D_   * FF_];
__device__ __nv_bfloat16 g_qlm [(size_t)VPAD_ * D_];
__device__ float g_sqkv[L_ * QKVD_];
__device__ float g_swo [L_ * D_ ];
__device__ float g_swfc[L_ * FF_];
__device__ float g_swpr[L_ * D_ ];
__device__ float g_slm [VPAD_];

__device__ float g_x  [S_ * D_ ];
__device__ __nv_bfloat16 g_hhi[S_ * D_ ];
__device__ __nv_bfloat16 g_hlo[S_ * D_ ];
__device__ float g_qkv[S_ * QKVD_];
__device__ float g_sc [(size_t)H_ * S_ * S_];
__device__ __nv_bfloat16 g_atthi[S_ * D_];
__device__ __nv_bfloat16 g_attlo[S_ * D_];
__device__ __nv_bfloat16 g_ffhi [S_ * FF_];
__device__ __nv_bfloat16 g_fflo [S_ * FF_];

__device__ __nv_bfloat16 g_qhi [S_ * D_ ];
__device__ __nv_bfloat16 g_qlo [S_ * D_ ];
__device__ __nv_bfloat16 g_khi [S_ * KVD_];
__device__ __nv_bfloat16 g_klo [S_ * KVD_];
__device__ __nv_bfloat16 g_vthi[KVD_ * S_];
__device__ __nv_bfloat16 g_vtlo[KVD_ * S_];
__device__ __nv_bfloat16 g_phi [(size_t)H_ * S_ * S_];
__device__ __nv_bfloat16 g_plo [(size_t)H_ * S_ * S_];

// ---------------- helpers ----------------
__device__ __forceinline__ u32 smem_u32(const void* p) {
    return (u32)__cvta_generic_to_shared(p);
}
__device__ __forceinline__ void cpasync16(u32 dst, const void* src) {
    asm volatile("cp.async.cg.shared.global [%0], [%1], 16;" :: "r"(dst), "l"(src));
}
__device__ __forceinline__ void ldm_x4(u32& r0, u32& r1, u32& r2, u32& r3, u32 a) {
    asm volatile("ldmatrix.sync.aligned.m8n8.x4.shared.b16 {%0,%1,%2,%3}, [%4];"
        : "=r"(r0), "=r"(r1), "=r"(r2), "=r"(r3) : "r"(a));
}
__device__ __forceinline__ void mma16816(float* d, const u32* a, const u32* b) {
    asm volatile("mma.sync.aligned.m16n8k16.row.col.f32.bf16.bf16.f32 "
        "{%0,%1,%2,%3}, {%4,%5,%6,%7}, {%8,%9}, {%0,%1,%2,%3};"
        : "+f"(d[0]), "+f"(d[1]), "+f"(d[2]), "+f"(d[3])
        : "r"(a[0]), "r"(a[1]), "r"(a[2]), "r"(a[3]), "r"(b[0]), "r"(b[1]));
}
__device__ __forceinline__ u32 sw_off(int r, int c) {      // 32-elem (64B) rows
    return (u32)(r * 64 + ((c ^ ((r >> 1) & 3)) << 4));
}
__device__ __forceinline__ u32 sw128(u32 b) {              // 64-elem (128B) rows
    return b ^ ((b >> 3) & 0x70u);
}
__device__ __forceinline__ void split_store(float v, __nv_bfloat16* hi, __nv_bfloat16* lo, size_t i) {
    __nv_bfloat16 h = __float2bfloat16(v);
    hi[i] = h;
    lo[i] = __float2bfloat16(v - __bfloat162float(h));
}

template<int W> __device__ __forceinline__ __nv_bfloat16* qsel() {
    if (W == 0) return g_qw;
    if (W == 1) return g_qwo;
    if (W == 2) return g_qwfc;
    if (W == 3) return g_qwpr;
    return g_qlm;
}
template<int W> __device__ __forceinline__ float* scsel() {
    if (W == 0) return g_sqkv;
    if (W == 1) return g_swo;
    if (W == 2) return g_swfc;
    if (W == 3) return g_swpr;
    return g_slm;
}
template<int A> __device__ __forceinline__ const __nv_bfloat16* ahisel() {
    if (A == 0) return g_hhi;
    if (A == 1) return g_atthi;
    return g_ffhi;
}
template<int A> __device__ __forceinline__ const __nv_bfloat16* alosel() {
    if (A == 0) return g_hlo;
    if (A == 1) return g_attlo;
    return g_fflo;
}

// ---------------- fake-quant (single pass, rows cached in registers) ----------------
template<int WSEL, int NR>
__global__ void quant_kernel(const float* __restrict__ W, int rpl, int ld, int off)
{
    const int n = NR * 256;
    int blk = blockIdx.x;
    int l = blk / rpl, r = blk % rpl;
    int out_row = l * ld + off + r;
    const float* w = W + (size_t)blk * n;
    __nv_bfloat16* qb = qsel<WSEL>() + (size_t)out_row * n;
    int tid = threadIdx.x;

    float v[NR];
    float m1 = 0.f, m2 = 0.f;
    #pragma unroll
    for (int j = 0; j < NR; j++) {
        v[j] = w[tid + j * 256];
        float a = fabsf(v[j]);
        if (a > m1) { m2 = m1; m1 = a; }
        else if (a > m2) { m2 = a; }
    }
    __shared__ float s1[256], s2[256];
    s1[tid] = m1; s2[tid] = m2;
    __syncthreads();
    for (int o = 128; o; o >>= 1) {
        if (tid < o) {
            float a1 = s1[tid], a2 = s2[tid];
            float b1 = s1[tid + o], b2 = s2[tid + o];
            s1[tid] = fmaxf(a1, b1);
            s2[tid] = fmaxf(fminf(a1, b1), fmaxf(a2, b2));
        }
        __syncthreads();
    }
    __shared__ float sh_clip, sh_scale;
    if (tid == 0) {
        float M1 = s1[0], M2 = s2[0];
        float idxf = 0.9999984f * (float)(n - 1);
        float frac = idxf - (float)(n - 2);
        float clip = M2 * (1.0f - frac) + M1 * frac;
        float scale = fmaxf(__fdiv_rn(clip, 127.0f), 1.0f / 127.0f);
        sh_clip = clip;
        sh_scale = scale;
        scsel<WSEL>()[out_row] = __half2float(__float2half_rn(scale));
    }
    __syncthreads();
    float clip = sh_clip, scale = sh_scale;
    #pragma unroll
    for (int j = 0; j < NR; j++) {
        float c = fminf(fmaxf(v[j], -clip), clip);
        float q = rintf(__fdiv_rn(c, scale));
        q = fminf(fmaxf(q, -127.f), 127.f);
        qb[tid + j * 256] = __float2bfloat16(q);
    }
}

// ---------------- embedding ----------------
__global__ void embed_kernel(const int* __restrict__ idx, const float* __restrict__ emb)
{
    int i = blockIdx.x * blockDim.x + threadIdx.x;
    int s = i >> 10, d = i & 1023;
    g_x[i] = emb[(size_t)idx[s] * D_ + d];
}

// ---------------- rmsnorm ----------------
__global__ void rmsnorm_split_kernel()
{
    int row = blockIdx.x;
    const float* xr = g_x + (size_t)row * D_;
    int tid = threadIdx.x;
    float ss = 0.f;
    for (int i = tid; i < D_; i += 256) { float v = xr[i]; ss += v * v; }
    __shared__ float sh[256];
    sh[tid] = ss; __syncthreads();
    for (int o = 128; o; o >>= 1) {
        if (tid < o) sh[tid] += sh[tid + o];
        __syncthreads();
    }
    float r = rsqrtf(sh[0] / (float)D_ + EPS_);
    for (int i = tid; i < D_; i += 256) {
        split_store(xr[i] * r, g_hhi, g_hlo, (size_t)row * D_ + i);
    }
}

// ---------------- per-head RMS + RoPE + gain ----------------
__global__ void qkpost_kernel(const float* __restrict__ gain, int nh, int off, int isq)
{
    int warp = (blockIdx.x * blockDim.x + threadIdx.x) >> 5;
    int lane = threadIdx.x & 31;
    int s = warp / nh, h = warp % nh;
    if (s >= S_) return;
    const float* base = g_qkv + (size_t)s * QKVD_ + off + h * HD_;
    float e0 = base[lane], e1 = base[lane + 32];
    float ss = e0 * e0 + e1 * e1;
    #pragma unroll
    for (int o = 16; o; o >>= 1) ss += __shfl_xor_sync(0xffffffffu, ss, o);
    float r = rsqrtf(ss * (1.f / 64.f) + EPS_);
    e0 *= r; e1 *= r;
    float inv = (float)exp(-((double)lane / 32.0) * 9.210340371976184);
    float f = (float)s * inv;
    float c  = (float)cos((double)f);
    float sn = (float)sin((double)f);
    float o0 =  e0 * c + e1 * sn;
    float o1 = -e0 * sn + e1 * c;
    if (isq) {
        float g = gain[h];
        split_store(o0 * g, g_qhi, g_qlo, (size_t)s * D_ + h * HD_ + lane);
        split_store(o1 * g, g_qhi, g_qlo, (size_t)s * D_ + h * HD_ + lane + 32);
    } else {
        split_store(o0, g_khi, g_klo, (size_t)s * KVD_ + h * HD_ + lane);
        split_store(o1, g_khi, g_klo, (size_t)s * KVD_ + h * HD_ + lane + 32);
    }
}

// ---------------- V transpose ----------------
__global__ void vtrans_kernel()
{
    __shared__ float t[32][33];
    int s0 = blockIdx.x * 32, c0 = blockIdx.y * 32;
    int tx = threadIdx.x, ty = threadIdx.y;
    #pragma unroll
    for (int k = 0; k < 32; k += 8)
        t[ty + k][tx] = g_qkv[(size_t)(s0 + ty + k) * QKVD_ + 1280 + c0 + tx];
    __syncthreads();
    #pragma unroll
    for (int k = 0; k < 32; k += 8) {
        float v = t[tx][ty + k];
        split_store(v, g_vthi, g_vtlo, (size_t)(c0 + ty + k) * S_ + s0 + tx);
    }
}

// ---------------- tensor-core scores ----------------
__global__ __launch_bounds__(128, 1) void tc_scores_kernel()
{
    int bi = blockIdx.y, bj = blockIdx.x, h = blockIdx.z;
    if (bj > bi) return;
    int kvh = h >> 2;

    __shared__ __align__(16) __nv_bfloat16 sQ[2][2][64 * 32];
    __shared__ __align__(16) __nv_bfloat16 sK[2][2][64 * 32];

    int tid = threadIdx.x, lane = tid & 31, wid = tid >> 5;
    int wm = wid & 1, wn = wid >> 1;
    u32 qb = smem_u32(&sQ[0][0][0]);
    u32 kb = smem_u32(&sK[0][0][0]);

    #pragma unroll
    for (int st = 0; st < 2; st++) {
        for (int id = tid; id < 64 * 4; id += 128) {
            int r = id >> 2, c = id & 3;
            u32 so = sw_off(r, c);
            size_t gq = (size_t)(bi * 64 + r) * D_ + h * HD_ + st * 32 + c * 8;
            cpasync16(qb + (u32)(st * 2 + 0) * 4096 + so, g_qhi + gq);
            cpasync16(qb + (u32)(st * 2 + 1) * 4096 + so, g_qlo + gq);
            size_t gk = (size_t)(bj * 64 + r) * KVD_ + kvh * HD_ + st * 32 + c * 8;
            cpasync16(kb + (u32)(st * 2 + 0) * 4096 + so, g_khi + gk);
            cpasync16(kb + (u32)(st * 2 + 1) * 4096 + so, g_klo + gk);
        }
    }
    asm volatile("cp.async.commit_group;");
    asm volatile("cp.async.wait_group 0;");
    __syncthreads();

    float acc[2][4][4];
    #pragma unroll
    for (int mi = 0; mi < 2; mi++)
        #pragma unroll
        for (int ni = 0; ni < 4; ni++) {
            acc[mi][ni][0] = 0.f; acc[mi][ni][1] = 0.f;
            acc[mi][ni][2] = 0.f; acc[mi][ni][3] = 0.f;
        }

    #pragma unroll
    for (int st = 0; st < 2; st++) {
        #pragma unroll
        for (int kc = 0; kc < 2; kc++) {
            u32 ah[2][4], al[2][4];
            #pragma unroll
            for (int mi = 0; mi < 2; mi++) {
                int lr = wm * 32 + mi * 16 + (lane & 15);
                int ch = kc * 2 + (lane >> 4);
                ldm_x4(ah[mi][0], ah[mi][1], ah[mi][2], ah[mi][3],
                       qb + (u32)(st * 2 + 0) * 4096 + sw_off(lr, ch));
                ldm_x4(al[mi][0], al[mi][1], al[mi][2], al[mi][3],
                       qb + (u32)(st * 2 + 1) * 4096 + sw_off(lr, ch));
            }
            u32 bh[4][2], bl[4][2];
            #pragma unroll
            for (int nj = 0; nj < 2; nj++) {
                int g = lane >> 3;
                int lr = wn * 32 + nj * 16 + (((g >> 1) & 1) << 3) + (lane & 7);
                int ch = kc * 2 + (g & 1);
                u32 r0, r1, r2, r3;
                ldm_x4(r0, r1, r2, r3, kb + (u32)(st * 2 + 0) * 4096 + sw_off(lr, ch));
                bh[nj * 2][0] = r0; bh[nj * 2][1] = r1;
                bh[nj * 2 + 1][0] = r2; bh[nj * 2 + 1][1] = r3;
                ldm_x4(r0, r1, r2, r3, kb + (u32)(st * 2 + 1) * 4096 + sw_off(lr, ch));
                bl[nj * 2][0] = r0; bl[nj * 2][1] = r1;
                bl[nj * 2 + 1][0] = r2; bl[nj * 2 + 1][1] = r3;
            }
            #pragma unroll
            for (int mi = 0; mi < 2; mi++) {
                #pragma unroll
                for (int ni = 0; ni < 4; ni++) {
                    mma16816(acc[mi][ni], ah[mi], bh[ni]);
                    mma16816(acc[mi][ni], ah[mi], bl[ni]);
                    mma16816(acc[mi][ni], al[mi], bh[ni]);
                }
            }
        }
    }

    #pragma unroll
    for (int mi = 0; mi < 2; mi++) {
        #pragma unroll
        for (int ni = 0; ni < 4; ni++) {
            int gi0 = bi * 64 + wm * 32 + mi * 16 + (lane >> 2);
            int gj0 = bj * 64 + wn * 32 + ni * 8 + ((lane & 3) << 1);
            #pragma unroll
            for (int half = 0; half < 2; half++) {
                int gi = gi0 + half * 8;
                #pragma unroll
                for (int e = 0; e < 2; e++) {
                    int gj = gj0 + e;
                    if (gj <= gi)
                        g_sc[((size_t)h * S_ + gi) * S_ + gj] = acc[mi][ni][half * 2 + e] * 0.125f;
                }
            }
        }
    }
}

// ---------------- causal softmax ----------------
__global__ void softmax_kernel()
{
    int i = blockIdx.x, h = blockIdx.y;
    const float* row = g_sc + ((size_t)h * S_ + i) * S_;
    __nv_bfloat16* phi = g_phi + ((size_t)h * S_ + i) * S_;
    __nv_bfloat16* plo = g_plo + ((size_t)h * S_ + i) * S_;
    int len = i + 1;
    int zlim = ((i >> 6) + 1) << 6;
    int tid = threadIdx.x;
    __shared__ float sh[256];
    float m = -FLT_MAX;
    for (int j = tid; j < len; j += 256) m = fmaxf(m, row[j]);
    sh[tid] = m; __syncthreads();
    for (int o = 128; o; o >>= 1) {
        if (tid < o) sh[tid] = fmaxf(sh[tid], sh[tid + o]);
        __syncthreads();
    }
    float M = sh[0];
    __syncthreads();
    float sum = 0.f;
    for (int j = tid; j < len; j += 256) sum += expf(row[j] - M);
    sh[tid] = sum; __syncthreads();
    for (int o = 128; o; o >>= 1) {
        if (tid < o) sh[tid] += sh[tid + o];
        __syncthreads();
    }
    float inv = 1.0f / sh[0];
    for (int j = tid; j < zlim; j += 256) {
        float p = (j < len) ? expf(row[j] - M) * inv : 0.0f;
        __nv_bfloat16 hb = __float2bfloat16(p);
        phi[j] = hb;
        plo[j] = __float2bfloat16(p - __bfloat162float(hb));
    }
}

// ---------------- tensor-core AV ----------------
__device__ __forceinline__ void av_load(int h, int kvh, int row0, int st, int k0,
                                        u32 pb, u32 vb, int tid)
{
    for (int id = tid; id < 64 * 4; id += 128) {
        int r = id >> 2, c = id & 3;
        u32 so = sw_off(r, c);
        size_t gp = ((size_t)h * S_ + row0 + r) * S_ + k0 + c * 8;
        cpasync16(pb + (u32)(st * 2 + 0) * 4096 + so, g_phi + gp);
        cpasync16(pb + (u32)(st * 2 + 1) * 4096 + so, g_plo + gp);
        size_t gv = (size_t)(kvh * 64 + r) * S_ + k0 + c * 8;
        cpasync16(vb + (u32)(st * 2 + 0) * 4096 + so, g_vthi + gv);
        cpasync16(vb + (u32)(st * 2 + 1) * 4096 + so, g_vtlo + gv);
    }
    asm volatile("cp.async.commit_group;");
}

__global__ __launch_bounds__(128, 1) void tc_av_kernel()
{
    int mt = blockIdx.x, h = blockIdx.y, kvh = h >> 2;
    int row0 = mt * 64;

    __shared__ __align__(16) __nv_bfloat16 sP[2][2][64 * 32];
    __shared__ __align__(16) __nv_bfloat16 sV[2][2][64 * 32];

    int tid = threadIdx.x, lane = tid & 31, wid = tid >> 5;
    int wm = wid & 1, wn = wid >> 1;
    u32 pb = smem_u32(&sP[0][0][0]);
    u32 vb = smem_u32(&sV[0][0][0]);

    float acc[2][4][4];
    #pragma unroll
    for (int mi = 0; mi < 2; mi++)
        #pragma unroll
        for (int ni = 0; ni < 4; ni++) {
            acc[mi][ni][0] = 0.f; acc[mi][ni][1] = 0.f;
            acc[mi][ni][2] = 0.f; acc[mi][ni][3] = 0.f;
        }

    int nIter = (row0 >> 5) + 2;
    av_load(h, kvh, row0, 0, 0, pb, vb, tid);

    for (int it = 0; it < nIter; it++) {
        if (it + 1 < nIter) {
            av_load(h, kvh, row0, (it + 1) & 1, (it + 1) << 5, pb, vb, tid);
            asm volatile("cp.async.wait_group 1;");
        } else {
            asm volatile("cp.async.wait_group 0;");
        }
        __syncthreads();

        int st = it & 1;
        #pragma unroll
        for (int kc = 0; kc < 2; kc++) {
            u32 ah[2][4], al[2][4];
            #pragma unroll
            for (int mi = 0; mi < 2; mi++) {
                int lr = wm * 32 + mi * 16 + (lane & 15);
                int ch = kc * 2 + (lane >> 4);
                ldm_x4(ah[mi][0], ah[mi][1], ah[mi][2], ah[mi][3],
                       pb + (u32)(st * 2 + 0) * 4096 + sw_off(lr, ch));
                ldm_x4(al[mi][0], al[mi][1], al[mi][2], al[mi][3],
                       pb + (u32)(st * 2 + 1) * 4096 + sw_off(lr, ch));
            }
            u32 bh[4][2], bl[4][2];
            #pragma unroll
            for (int nj = 0; nj < 2; nj++) {
                int g = lane >> 3;
                int lr = wn * 32 + nj * 16 + (((g >> 1) & 1) << 3) + (lane & 7);
                int ch = kc * 2 + (g & 1);
                u32 r0, r1, r2, r3;
                ldm_x4(r0, r1, r2, r3, vb + (u32)(st * 2 + 0) * 4096 + sw_off(lr, ch));
                bh[nj * 2][0] = r0; bh[nj * 2][1] = r1;
                bh[nj * 2 + 1][0] = r2; bh[nj * 2 + 1][1] = r3;
                ldm_x4(r0, r1, r2, r3, vb + (u32)(st * 2 + 1) * 4096 + sw_off(lr, ch));
                bl[nj * 2][0] = r0; bl[nj * 2][1] = r1;
                bl[nj * 2 + 1][0] = r2; bl[nj * 2 + 1][1] = r3;
            }
            #pragma unroll
            for (int mi = 0; mi < 2; mi++) {
                #pragma unroll
                for (int ni = 0; ni < 4; ni++) {
                    mma16816(acc[mi][ni], ah[mi], bh[ni]);
                    mma16816(acc[mi][ni], ah[mi], bl[ni]);
                    mma16816(acc[mi][ni], al[mi], bh[ni]);
                }
            }
        }
        __syncthreads();
    }

    #pragma unroll
    for (int mi = 0; mi < 2; mi++) {
        #pragma unroll
        for (int ni = 0; ni < 4; ni++) {
            int gi0 = row0 + wm * 32 + mi * 16 + (lane >> 2);
            int gd0 = wn * 32 + ni * 8 + ((lane & 3) << 1);
            #pragma unroll
            for (int half = 0; half < 2; half++) {
                int gi = gi0 + half * 8;
                #pragma unroll
                for (int e = 0; e < 2; e++) {
                    int gd = gd0 + e;
                    split_store(acc[mi][ni][half * 2 + e], g_atthi, g_attlo,
                                (size_t)gi * D_ + h * HD_ + gd);
                }
            }
        }
    }
}

// ---------------- weight GEMM: BK=64, 3-stage cp.async pipeline, 128B-row swizzle ----------------
template<int BM, int BN>
__device__ __forceinline__ void load_stage64(
    const __nv_bfloat16* Ahi, const __nv_bfloat16* Alo, const __nv_bfloat16* Bq,
    u32 sbase, int row0, int col0, int K, int k0, int tid)
{
    constexpr u32 ABYTES = (u32)BM * 128;
    for (int id = tid; id < BM * 8; id += 256) {
        int r = id >> 3, ck = id & 7;
        u32 so = sw128((u32)(r * 128 + ck * 16));
        size_t g = (size_t)(row0 + r) * K + k0 + ck * 8;
        cpasync16(sbase + so, Ahi + g);
        cpasync16(sbase + ABYTES + so, Alo + g);
    }
    for (int id = tid; id < BN * 8; id += 256) {
        int r = id >> 3, ck = id & 7;
        u32 so = sw128((u32)(r * 128 + ck * 16));
        cpasync16(sbase + 2 * ABYTES + so, Bq + (size_t)(col0 + r) * K + k0 + ck * 8);
    }
    asm volatile("cp.async.commit_group;");
}

// EPI: 0 = write g_qkv, 1 = residual add into g_x, 2 = relu^2 split into g_ff, 3 = write Cout
template<int BM, int BN, int WM, int WN, int EPI, int WSEL, int ASEL>
__global__ __launch_bounds__(256, 1)
void qgemm_kernel(float* __restrict__ Cout, int layer, int N, int K, int ldc)
{
    constexpr int TM = BM / WM, TN = BN / WN;
    constexpr int MI = TM / 16, NI = TN / 8;
    constexpr u32 STB = (u32)(2 * BM + BN) * 128;

    extern __shared__ char dsm[];
    u32 base = (smem_u32(dsm) + 1023u) & ~1023u;

    int tid = threadIdx.x, lane = tid & 31, wid = tid >> 5;
    int wm = wid % WM, wn = wid / WM;
    int row0 = blockIdx.y * BM, col0 = blockIdx.x * BN;

    const __nv_bfloat16* Ahi = ahisel<ASEL>();
    const __nv_bfloat16* Alo = alosel<ASEL>();
    const __nv_bfloat16* Bq  = qsel<WSEL>() + (size_t)layer * N * K;
    const float* Sc = scsel<WSEL>() + (size_t)layer * N;

    float acc[MI][NI][4];
    #pragma unroll
    for (int mi = 0; mi < MI; mi++) {
        #pragma unroll
        for (int ni = 0; ni < NI; ni++) {
            acc[mi][ni][0] = 0.f; acc[mi][ni][1] = 0.f;
            acc[mi][ni][2] = 0.f; acc[mi][ni][3] = 0.f;
        }
    }

    int n = K >> 6;
    load_stage64<BM, BN>(Ahi, Alo, Bq, base,       row0, col0, K, 0,  tid);
    load_stage64<BM, BN>(Ahi, Alo, Bq, base + STB, row0, col0, K, 64, tid);

    for (int it = 0; it < n; it++) {
        asm volatile("cp.async.wait_group 1;");
        __syncthreads();

        int ldst = it + 2;
        if (ldst < n) {
            int buf = ldst % 3;
            load_stage64<BM, BN>(Ahi, Alo, Bq, base + (u32)buf * STB,
                                 row0, col0, K, ldst << 6, tid);
        } else {
            asm volatile("cp.async.commit_group;");
        }

        u32 sb = base + (u32)(it % 3) * STB;
        #pragma unroll
        for (int kc = 0; kc < 4; kc++) {
            u32 ah[MI][4], al[MI][4];
            #pragma unroll
            for (int mi = 0; mi < MI; mi++) {
                int lr = wm * TM + mi * 16 + (lane & 15);
                int ch = kc * 2 + (lane >> 4);
                u32 so = sw128((u32)(lr * 128 + ch * 16));
                ldm_x4(ah[mi][0], ah[mi][1], ah[mi][2], ah[mi][3], sb + so);
                ldm_x4(al[mi][0], al[mi][1], al[mi][2], al[mi][3], sb + (u32)BM * 128 + so);
            }
            u32 bb[NI][2];
            #pragma unroll
            for (int nj = 0; nj < NI / 2; nj++) {
                int g = lane >> 3;
                int lr = wn * TN + nj * 16 + (((g >> 1) & 1) << 3) + (lane & 7);
                int ch = kc * 2 + (g & 1);
                u32 r0, r1, r2, r3;
                ldm_x4(r0, r1, r2, r3, sb + 2u * BM * 128 + sw128((u32)(lr * 128 + ch * 16)));
                bb[nj * 2][0] = r0; bb[nj * 2][1] = r1;
                bb[nj * 2 + 1][0] = r2; bb[nj * 2 + 1][1] = r3;
            }
            #pragma unroll
            for (int mi = 0; mi < MI; mi++) {
                #pragma unroll
                for (int ni = 0; ni < NI; ni++) {
                    mma16816(acc[mi][ni], ah[mi], bb[ni]);
                    mma16816(acc[mi][ni], al[mi], bb[ni]);
                }
            }
        }
    }

    #pragma unroll
    for (int mi = 0; mi < MI; mi++) {
        #pragma unroll
        for (int ni = 0; ni < NI; ni++) {
            int gr0 = row0 + wm * TM + mi * 16 + (lane >> 2);
            int gc  = col0 + wn * TN + ni * 8 + ((lane & 3) << 1);
            #pragma unroll
            for (int half = 0; half < 2; half++) {
                int gr = gr0 + half * 8;
                #pragma unroll
                for (int e = 0; e < 2; e++) {
                    int c = gc + e;
                    if (c >= N) continue;
                    float v = acc[mi][ni][half * 2 + e] * Sc[c];
                    if (EPI == 0) {
                        g_qkv[(size_t)gr * QKVD_ + c] = v;
                    } else if (EPI == 1) {
                        g_x[(size_t)gr * D_ + c] += v;
                    } else if (EPI == 2) {
                        float t = fmaxf(v, 0.f);
                        split_store(t * t, g_ffhi, g_fflo, (size_t)gr * FF_ + c);
                    } else {
                        Cout[(size_t)gr * ldc + c] = v;
                    }
                }
            }
        }
    }
}

#define DSM_SMALL (3 * (2 * 128 + 64)  * 128 + 1024)
#define DSM_BIG   (3 * (2 * 128 + 128) * 128 + 1024)

// ---------------- host orchestration ----------------
extern "C" void kernel_launch(void* const* d_in, const int* in_sizes, int n_in,
                              void* d_out, int out_size)
{
    (void)in_sizes; (void)n_in; (void)out_size;
    const int*   idx = (const int*)  d_in[0];
    const float* emb = (const float*)d_in[1];
    const float* wq  = (const float*)d_in[2];
    const float* wk  = (const float*)d_in[3];
    const float* wv  = (const float*)d_in[4];
    const float* wo  = (const float*)d_in[5];
    const float* qg  = (const float*)d_in[6];
    const float* wfc = (const float*)d_in[7];
    const float* wpr = (const float*)d_in[8];
    const float* lm  = (const float*)d_in[9];
    float* out = (float*)d_out;

    cudaFuncSetAttribute(qgemm_kernel<128, 64, 4, 2, 0, 0, 0>,
                         cudaFuncAttributeMaxDynamicSharedMemorySize, DSM_SMALL);
    cudaFuncSetAttribute(qgemm_kernel<128, 64, 4, 2, 1, 1, 1>,
                         cudaFuncAttributeMaxDynamicSharedMemorySize, DSM_SMALL);
    cudaFuncSetAttribute(qgemm_kernel<128, 128, 2, 4, 2, 2, 0>,
                         cudaFuncAttributeMaxDynamicSharedMemorySize, DSM_BIG);
    cudaFuncSetAttribute(qgemm_kernel<128, 64, 4, 2, 1, 3, 2>,
                         cudaFuncAttributeMaxDynamicSharedMemorySize, DSM_SMALL);
    cudaFuncSetAttribute(qgemm_kernel<128, 128, 2, 4, 3, 4, 0>,
                         cudaFuncAttributeMaxDynamicSharedMemorySize, DSM_BIG);

    quant_kernel<0, 4><<<L_ * D_,    256>>>(wq,  D_,   QKVD_, 0);
    quant_kernel<0, 4><<<L_ * KVD_,  256>>>(wk,  KVD_, QKVD_, 1024);
    quant_kernel<0, 4><<<L_ * KVD_,  256>>>(wv,  KVD_, QKVD_, 1280);
    quant_kernel<1, 4><<<L_ * D_,    256>>>(wo,  L_ * D_,  0, 0);
    quant_kernel<2, 4><<<L_ * FF_,   256>>>(wfc, L_ * FF_, 0, 0);
    quant_kernel<3, 16><<<L_ * D_,   256>>>(wpr, L_ * D_,  0, 0);
    quant_kernel<4, 4><<<V_,         256>>>(lm,  V_,       0, 0);

    embed_kernel<<<(S_ * D_) / 256, 256>>>(idx, emb);

    for (int l = 0; l < L_; l++) {
        rmsnorm_split_kernel<<<S_, 256>>>();

        qgemm_kernel<128, 64, 4, 2, 0, 0, 0><<<dim3(QKVD_ / 64, S_ / 128), 256, DSM_SMALL>>>(
            nullptr, l, QKVD_, D_, QKVD_);

        qkpost_kernel<<<(S_ * H_)  / 4, 128>>>(qg + l * H_, H_,  0,    1);
        qkpost_kernel<<<(S_ * KV_) / 4, 128>>>(nullptr,     KV_, 1024, 0);
        vtrans_kernel<<<dim3(S_ / 32, KVD_ / 32), dim3(32, 8)>>>();

        tc_scores_kernel<<<dim3(16, 16, H_), 128>>>();
        softmax_kernel<<<dim3(S_, H_), 256>>>();
        tc_av_kernel<<<dim3(16, H_), 128>>>();

        qgemm_kernel<128, 64, 4, 2, 1, 1, 1><<<dim3(D_ / 64, S_ / 128), 256, DSM_SMALL>>>(
            nullptr, l, D_, D_, D_);

        rmsnorm_split_kernel<<<S_, 256>>>();

        qgemm_kernel<128, 128, 2, 4, 2, 2, 0><<<dim3(FF_ / 128, S_ / 128), 256, DSM_BIG>>>(
            nullptr, l, FF_, D_, FF_);

        qgemm_kernel<128, 64, 4, 2, 1, 3, 2><<<dim3(D_ / 64, S_ / 128), 256, DSM_SMALL>>>(
            nullptr, l, D_, FF_, D_);
    }

    rmsnorm_split_kernel<<<S_, 256>>>();
    qgemm_kernel<128, 128, 2, 4, 3, 4, 0><<<dim3(VPAD_ / 128, S_ / 128), 256, DSM_BIG>>>(
        out, 0, V_, D_, V_);
}

// round 9
// speedup vs baseline: 6.5960x; 1.1103x over previous
#include <cuda_runtime.h>
#include <cuda_fp16.h>
#include <cuda_bf16.h>
#include <stdint.h>
#include <cstdint>
#include <math.h>
#include <float.h>

typedef unsigned int u32;

#define S_   1024
#define D_   1024
#define H_   16
#define KV_  4
#define HD_  64
#define KVD_ 256
#define FF_  4096
#define L_   8
#define V_   50257
#define VPAD_ 50304
#define QKVD_ 1536
#define EPS_ 1.1920928955078125e-07f

// ---------------- device globals ----------------
__device__ __nv_bfloat16 g_qw  [L_ * QKVD_ * D_];
__device__ __nv_bfloat16 g_qwo [L_ * D_   * D_ ];
__device__ __nv_bfloat16 g_qwfc[L_ * FF_  * D_ ];
__device__ __nv_bfloat16 g_qwpr[L_ * D_   * FF_];
__device__ __nv_bfloat16 g_qlm [(size_t)VPAD_ * D_];
__device__ float g_sqkv[L_ * QKVD_];
__device__ float g_swo [L_ * D_ ];
__device__ float g_swfc[L_ * FF_];
__device__ float g_swpr[L_ * D_ ];
__device__ float g_slm [VPAD_];

__device__ float g_x  [S_ * D_ ];
__device__ __nv_bfloat16 g_hhi[S_ * D_ ];
__device__ __nv_bfloat16 g_hlo[S_ * D_ ];
__device__ float g_qkv[S_ * QKVD_];
__device__ __nv_bfloat16 g_atthi[S_ * D_];
__device__ __nv_bfloat16 g_attlo[S_ * D_];
__device__ __nv_bfloat16 g_ffhi [S_ * FF_];
__device__ __nv_bfloat16 g_fflo [S_ * FF_];

__device__ __nv_bfloat16 g_qhi [S_ * D_ ];
__device__ __nv_bfloat16 g_qlo [S_ * D_ ];
__device__ __nv_bfloat16 g_khi [S_ * KVD_];
__device__ __nv_bfloat16 g_klo [S_ * KVD_];
__device__ __nv_bfloat16 g_vthi[KVD_ * S_];
__device__ __nv_bfloat16 g_vtlo[KVD_ * S_];

// ---------------- helpers ----------------
__device__ __forceinline__ u32 smem_u32(const void* p) {
    return (u32)__cvta_generic_to_shared(p);
}
__device__ __forceinline__ void cpasync16(u32 dst, const void* src) {
    asm volatile("cp.async.cg.shared.global [%0], [%1], 16;" :: "r"(dst), "l"(src));
}
__device__ __forceinline__ void ldm_x4(u32& r0, u32& r1, u32& r2, u32& r3, u32 a) {
    asm volatile("ldmatrix.sync.aligned.m8n8.x4.shared.b16 {%0,%1,%2,%3}, [%4];"
        : "=r"(r0), "=r"(r1), "=r"(r2), "=r"(r3) : "r"(a));
}
__device__ __forceinline__ void mma16816(float* d, const u32* a, const u32* b) {
    asm volatile("mma.sync.aligned.m16n8k16.row.col.f32.bf16.bf16.f32 "
        "{%0,%1,%2,%3}, {%4,%5,%6,%7}, {%8,%9}, {%0,%1,%2,%3};"
        : "+f"(d[0]), "+f"(d[1]), "+f"(d[2]), "+f"(d[3])
        : "r"(a[0]), "r"(a[1]), "r"(a[2]), "r"(a[3]), "r"(b[0]), "r"(b[1]));
}
__device__ __forceinline__ u32 sw128(u32 b) {              // 128B rows
    return b ^ ((b >> 3) & 0x70u);
}
__device__ __forceinline__ void split_store(float v, __nv_bfloat16* hi, __nv_bfloat16* lo, size_t i) {
    __nv_bfloat16 h = __float2bfloat16(v);
    hi[i] = h;
    lo[i] = __float2bfloat16(v - __bfloat162float(h));
}
// pack (a,b) into bf16x2 hi reg + residual lo reg
__device__ __forceinline__ void split2(float a, float b, u32& hi, u32& lo) {
    __nv_bfloat16 ha = __float2bfloat16(a), hb = __float2bfloat16(b);
    hi = (u32)__bfloat16_as_ushort(ha) | ((u32)__bfloat16_as_ushort(hb) << 16);
    lo = (u32)__bfloat16_as_ushort(__float2bfloat16(a - __bfloat162float(ha)))
       | ((u32)__bfloat16_as_ushort(__float2bfloat16(b - __bfloat162float(hb))) << 16);
}

template<int W> __device__ __forceinline__ __nv_bfloat16* qsel() {
    if (W == 0) return g_qw;
    if (W == 1) return g_qwo;
    if (W == 2) return g_qwfc;
    if (W == 3) return g_qwpr;
    return g_qlm;
}
template<int W> __device__ __forceinline__ float* scsel() {
    if (W == 0) return g_sqkv;
    if (W == 1) return g_swo;
    if (W == 2) return g_swfc;
    if (W == 3) return g_swpr;
    return g_slm;
}
template<int A> __device__ __forceinline__ const __nv_bfloat16* ahisel() {
    if (A == 0) return g_hhi;
    if (A == 1) return g_atthi;
    return g_ffhi;
}
template<int A> __device__ __forceinline__ const __nv_bfloat16* alosel() {
    if (A == 0) return g_hlo;
    if (A == 1) return g_attlo;
    return g_fflo;
}

// ---------------- fake-quant ----------------
template<int WSEL, int NR>
__global__ void quant_kernel(const float* __restrict__ W, int rpl, int ld, int off)
{
    const int n = NR * 256;
    int blk = blockIdx.x;
    int l = blk / rpl, r = blk % rpl;
    int out_row = l * ld + off + r;
    const float* w = W + (size_t)blk * n;
    __nv_bfloat16* qb = qsel<WSEL>() + (size_t)out_row * n;
    int tid = threadIdx.x;

    float v[NR];
    float m1 = 0.f, m2 = 0.f;
    #pragma unroll
    for (int j = 0; j < NR; j++) {
        v[j] = w[tid + j * 256];
        float a = fabsf(v[j]);
        if (a > m1) { m2 = m1; m1 = a; }
        else if (a > m2) { m2 = a; }
    }
    __shared__ float s1[256], s2[256];
    s1[tid] = m1; s2[tid] = m2;
    __syncthreads();
    for (int o = 128; o; o >>= 1) {
        if (tid < o) {
            float a1 = s1[tid], a2 = s2[tid];
            float b1 = s1[tid + o], b2 = s2[tid + o];
            s1[tid] = fmaxf(a1, b1);
            s2[tid] = fmaxf(fminf(a1, b1), fmaxf(a2, b2));
        }
        __syncthreads();
    }
    __shared__ float sh_clip, sh_scale;
    if (tid == 0) {
        float M1 = s1[0], M2 = s2[0];
        float idxf = 0.9999984f * (float)(n - 1);
        float frac = idxf - (float)(n - 2);
        float clip = M2 * (1.0f - frac) + M1 * frac;
        float scale = fmaxf(__fdiv_rn(clip, 127.0f), 1.0f / 127.0f);
        sh_clip = clip;
        sh_scale = scale;
        scsel<WSEL>()[out_row] = __half2float(__float2half_rn(scale));
    }
    __syncthreads();
    float clip = sh_clip, scale = sh_scale;
    #pragma unroll
    for (int j = 0; j < NR; j++) {
        float c = fminf(fmaxf(v[j], -clip), clip);
        float q = rintf(__fdiv_rn(c, scale));
        q = fminf(fmaxf(q, -127.f), 127.f);
        qb[tid + j * 256] = __float2bfloat16(q);
    }
}

// ---------------- embedding ----------------
__global__ void embed_kernel(const int* __restrict__ idx, const float* __restrict__ emb)
{
    int i = blockIdx.x * blockDim.x + threadIdx.x;
    int s = i >> 10, d = i & 1023;
    g_x[i] = emb[(size_t)idx[s] * D_ + d];
}

// ---------------- rmsnorm ----------------
__global__ void rmsnorm_split_kernel()
{
    int row = blockIdx.x;
    const float* xr = g_x + (size_t)row * D_;
    int tid = threadIdx.x;
    float ss = 0.f;
    for (int i = tid; i < D_; i += 256) { float v = xr[i]; ss += v * v; }
    __shared__ float sh[256];
    sh[tid] = ss; __syncthreads();
    for (int o = 128; o; o >>= 1) {
        if (tid < o) sh[tid] += sh[tid + o];
        __syncthreads();
    }
    float r = rsqrtf(sh[0] / (float)D_ + EPS_);
    for (int i = tid; i < D_; i += 256) {
        split_store(xr[i] * r, g_hhi, g_hlo, (size_t)row * D_ + i);
    }
}

// ---------------- per-head RMS + RoPE + gain (q pre-scaled by 1/8) ----------------
__global__ void qkpost_kernel(const float* __restrict__ gain, int nh, int off, int isq)
{
    int warp = (blockIdx.x * blockDim.x + threadIdx.x) >> 5;
    int lane = threadIdx.x & 31;
    int s = warp / nh, h = warp % nh;
    if (s >= S_) return;
    const float* base = g_qkv + (size_t)s * QKVD_ + off + h * HD_;
    float e0 = base[lane], e1 = base[lane + 32];
    float ss = e0 * e0 + e1 * e1;
    #pragma unroll
    for (int o = 16; o; o >>= 1) ss += __shfl_xor_sync(0xffffffffu, ss, o);
    float r = rsqrtf(ss * (1.f / 64.f) + EPS_);
    e0 *= r; e1 *= r;
    float inv = (float)exp(-((double)lane / 32.0) * 9.210340371976184);
    float f = (float)s * inv;
    float c  = (float)cos((double)f);
    float sn = (float)sin((double)f);
    float o0 =  e0 * c + e1 * sn;
    float o1 = -e0 * sn + e1 * c;
    if (isq) {
        float g = gain[h] * 0.125f;    // fold 1/sqrt(64) into q
        split_store(o0 * g, g_qhi, g_qlo, (size_t)s * D_ + h * HD_ + lane);
        split_store(o1 * g, g_qhi, g_qlo, (size_t)s * D_ + h * HD_ + lane + 32);
    } else {
        split_store(o0, g_khi, g_klo, (size_t)s * KVD_ + h * HD_ + lane);
        split_store(o1, g_khi, g_klo, (size_t)s * KVD_ + h * HD_ + lane + 32);
    }
}

// ---------------- V transpose ----------------
__global__ void vtrans_kernel()
{
    __shared__ float t[32][33];
    int s0 = blockIdx.x * 32, c0 = blockIdx.y * 32;
    int tx = threadIdx.x, ty = threadIdx.y;
    #pragma unroll
    for (int k = 0; k < 32; k += 8)
        t[ty + k][tx] = g_qkv[(size_t)(s0 + ty + k) * QKVD_ + 1280 + c0 + tx];
    __syncthreads();
    #pragma unroll
    for (int k = 0; k < 32; k += 8) {
        float v = t[tx][ty + k];
        split_store(v, g_vthi, g_vtlo, (size_t)(c0 + ty + k) * S_ + s0 + tx);
    }
}

// ---------------- fused flash attention ----------------
// block: (bi, h). 4 warps, warp w owns rows bi*64 + w*16 .. +16. kv tiles of 64.
// smem: Q hi/lo 16KB @ base, then 2 stages x (K hi, K lo, Vt hi, Vt lo) 32KB each.
#define FA_DSM (16384 + 2 * 32768 + 1024)

__global__ __launch_bounds__(128, 1) void flash_kernel()
{
    int bi = 15 - (int)blockIdx.x;      // longest blocks first
    int h = blockIdx.y, kvh = h >> 2;
    extern __shared__ char fsm[];
    u32 base = (smem_u32(fsm) + 1023u) & ~1023u;

    int tid = threadIdx.x, lane = tid & 31, w = tid >> 5;
    int tig = lane & 3, grp = lane >> 2;

    // Q tile load (hi @ base, lo @ base+8192)
    for (int id = tid; id < 512; id += 128) {
        int r = id >> 3, ck = id & 7;
        u32 so = sw128((u32)(r * 128 + ck * 16));
        size_t gq = (size_t)(bi * 64 + r) * D_ + h * HD_ + ck * 8;
        cpasync16(base + so, g_qhi + gq);
        cpasync16(base + 8192 + so, g_qlo + gq);
    }
    asm volatile("cp.async.commit_group;");

    #define FA_LOAD(st, jt) do { \
        u32 sb_ = base + 16384 + (u32)(st) * 32768; \
        for (int id_ = tid; id_ < 512; id_ += 128) { \
            int r_ = id_ >> 3, ck_ = id_ & 7; \
            u32 so_ = sw128((u32)(r_ * 128 + ck_ * 16)); \
            size_t gk_ = (size_t)((jt) * 64 + r_) * KVD_ + kvh * HD_ + ck_ * 8; \
            cpasync16(sb_ + so_,         g_khi + gk_); \
            cpasync16(sb_ + 8192 + so_,  g_klo + gk_); \
            size_t gv_ = (size_t)(kvh * 64 + r_) * S_ + (jt) * 64 + ck_ * 8; \
            cpasync16(sb_ + 16384 + so_, g_vthi + gv_); \
            cpasync16(sb_ + 24576 + so_, g_vtlo + gv_); \
        } \
        asm volatile("cp.async.commit_group;"); \
    } while (0)

    int n = bi + 1;
    FA_LOAD(0, 0);

    // Q fragments (A layout), hi/lo
    asm volatile("cp.async.wait_group 1;");
    __syncthreads();
    u32 qh[4][4], ql[4][4];
    #pragma unroll
    for (int kc = 0; kc < 4; kc++) {
        int lr = w * 16 + (lane & 15);
        int ch = kc * 2 + (lane >> 4);
        u32 so = sw128((u32)(lr * 128 + ch * 16));
        ldm_x4(qh[kc][0], qh[kc][1], qh[kc][2], qh[kc][3], base + so);
        ldm_x4(ql[kc][0], ql[kc][1], ql[kc][2], ql[kc][3], base + 8192 + so);
    }

    float o[8][4];
    #pragma unroll
    for (int nd = 0; nd < 8; nd++) { o[nd][0]=0.f; o[nd][1]=0.f; o[nd][2]=0.f; o[nd][3]=0.f; }
    float m0 = -1e30f, m1 = -1e30f, l0 = 0.f, l1 = 0.f;

    for (int jt = 0; jt < n; jt++) {
        if (jt + 1 < n) {
            FA_LOAD((jt + 1) & 1, jt + 1);
            asm volatile("cp.async.wait_group 1;");
        } else {
            asm volatile("cp.async.wait_group 0;");
        }
        __syncthreads();

        u32 kb = base + 16384 + (u32)(jt & 1) * 32768;

        // ---- S = Q K^T (pre-scaled by 1/8 via q) ----
        float s[8][4];
        #pragma unroll
        for (int ni = 0; ni < 8; ni++) { s[ni][0]=0.f; s[ni][1]=0.f; s[ni][2]=0.f; s[ni][3]=0.f; }
        #pragma unroll
        for (int kc = 0; kc < 4; kc++) {
            u32 bh[8][2], bl[8][2];
            #pragma unroll
            for (int nj = 0; nj < 4; nj++) {
                int g = lane >> 3;
                int lr = nj * 16 + (((g >> 1) & 1) << 3) + (lane & 7);
                int ch = kc * 2 + (g & 1);
                u32 so = sw128((u32)(lr * 128 + ch * 16));
                u32 r0, r1, r2, r3;
                ldm_x4(r0, r1, r2, r3, kb + so);
                bh[nj * 2][0] = r0; bh[nj * 2][1] = r1;
                bh[nj * 2 + 1][0] = r2; bh[nj * 2 + 1][1] = r3;
                ldm_x4(r0, r1, r2, r3, kb + 8192 + so);
                bl[nj * 2][0] = r0; bl[nj * 2][1] = r1;
                bl[nj * 2 + 1][0] = r2; bl[nj * 2 + 1][1] = r3;
            }
            #pragma unroll
            for (int ni = 0; ni < 8; ni++) {
                mma16816(s[ni], qh[kc], bh[ni]);
                mma16816(s[ni], qh[kc], bl[ni]);
                mma16816(s[ni], ql[kc], bh[ni]);
            }
        }

        // ---- causal mask on diagonal tile ----
        if (jt == bi) {
            int ci0 = w * 16 + grp, ci1 = ci0 + 8;
            #pragma unroll
            for (int ni = 0; ni < 8; ni++) {
                int cj = ni * 8 + tig * 2;
                if (cj     > ci0) s[ni][0] = -1e30f;
                if (cj + 1 > ci0) s[ni][1] = -1e30f;
                if (cj     > ci1) s[ni][2] = -1e30f;
                if (cj + 1 > ci1) s[ni][3] = -1e30f;
            }
        }

        // ---- online softmax ----
        float tm0 = -1e30f, tm1 = -1e30f;
        #pragma unroll
        for (int ni = 0; ni < 8; ni++) {
            tm0 = fmaxf(tm0, fmaxf(s[ni][0], s[ni][1]));
            tm1 = fmaxf(tm1, fmaxf(s[ni][2], s[ni][3]));
        }
        tm0 = fmaxf(tm0, __shfl_xor_sync(0xffffffffu, tm0, 1));
        tm0 = fmaxf(tm0, __shfl_xor_sync(0xffffffffu, tm0, 2));
        tm1 = fmaxf(tm1, __shfl_xor_sync(0xffffffffu, tm1, 1));
        tm1 = fmaxf(tm1, __shfl_xor_sync(0xffffffffu, tm1, 2));
        float mn0 = fmaxf(m0, tm0), mn1 = fmaxf(m1, tm1);
        float a0 = expf(m0 - mn0), a1 = expf(m1 - mn1);
        m0 = mn0; m1 = mn1;

        float rs0 = 0.f, rs1 = 0.f;
        #pragma unroll
        for (int ni = 0; ni < 8; ni++) {
            s[ni][0] = expf(s[ni][0] - mn0);
            s[ni][1] = expf(s[ni][1] - mn0);
            s[ni][2] = expf(s[ni][2] - mn1);
            s[ni][3] = expf(s[ni][3] - mn1);
            rs0 += s[ni][0] + s[ni][1];
            rs1 += s[ni][2] + s[ni][3];
        }
        rs0 += __shfl_xor_sync(0xffffffffu, rs0, 1);
        rs0 += __shfl_xor_sync(0xffffffffu, rs0, 2);
        rs1 += __shfl_xor_sync(0xffffffffu, rs1, 1);
        rs1 += __shfl_xor_sync(0xffffffffu, rs1, 2);
        l0 = l0 * a0 + rs0;
        l1 = l1 * a1 + rs1;
        #pragma unroll
        for (int nd = 0; nd < 8; nd++) {
            o[nd][0] *= a0; o[nd][1] *= a0;
            o[nd][2] *= a1; o[nd][3] *= a1;
        }

        // ---- O += P V (P repacked in-register) ----
        u32 vbh = kb + 16384, vbl = kb + 24576;
        #pragma unroll
        for (int kc = 0; kc < 4; kc++) {
            u32 pah[4], pal[4];
            split2(s[2 * kc][0],     s[2 * kc][1],     pah[0], pal[0]);
            split2(s[2 * kc][2],     s[2 * kc][3],     pah[1], pal[1]);
            split2(s[2 * kc + 1][0], s[2 * kc + 1][1], pah[2], pal[2]);
            split2(s[2 * kc + 1][2], s[2 * kc + 1][3], pah[3], pal[3]);
            u32 vh[8][2], vl[8][2];
            #pragma unroll
            for (int nj = 0; nj < 4; nj++) {
                int g = lane >> 3;
                int lr = nj * 16 + (((g >> 1) & 1) << 3) + (lane & 7);
                int ch = kc * 2 + (g & 1);
                u32 so = sw128((u32)(lr * 128 + ch * 16));
                u32 r0, r1, r2, r3;
                ldm_x4(r0, r1, r2, r3, vbh + so);
                vh[nj * 2][0] = r0; vh[nj * 2][1] = r1;
                vh[nj * 2 + 1][0] = r2; vh[nj * 2 + 1][1] = r3;
                ldm_x4(r0, r1, r2, r3, vbl + so);
                vl[nj * 2][0] = r0; vl[nj * 2][1] = r1;
                vl[nj * 2 + 1][0] = r2; vl[nj * 2 + 1][1] = r3;
            }
            #pragma unroll
            for (int nd = 0; nd < 8; nd++) {
                mma16816(o[nd], pah, vh[nd]);
                mma16816(o[nd], pah, vl[nd]);
                mma16816(o[nd], pal, vh[nd]);
            }
        }
        __syncthreads();
    }

    // ---- finalize: divide by row sum, write att hi/lo ----
    float inv0 = 1.0f / l0, inv1 = 1.0f / l1;
    int gi0 = bi * 64 + w * 16 + grp;
    #pragma unroll
    for (int nd = 0; nd < 8; nd++) {
        int gd = h * HD_ + nd * 8 + tig * 2;
        split_store(o[nd][0] * inv0, g_atthi, g_attlo, (size_t)gi0 * D_ + gd);
        split_store(o[nd][1] * inv0, g_atthi, g_attlo, (size_t)gi0 * D_ + gd + 1);
        split_store(o[nd][2] * inv1, g_atthi, g_attlo, (size_t)(gi0 + 8) * D_ + gd);
        split_store(o[nd][3] * inv1, g_atthi, g_attlo, (size_t)(gi0 + 8) * D_ + gd + 1);
    }
    #undef FA_LOAD
}

// ---------------- weight GEMM (R8: BK=64, 3-stage pipeline) ----------------
template<int BM, int BN>
__device__ __forceinline__ void load_stage64(
    const __nv_bfloat16* Ahi, const __nv_bfloat16* Alo, const __nv_bfloat16* Bq,
    u32 sbase, int row0, int col0, int K, int k0, int tid)
{
    constexpr u32 ABYTES = (u32)BM * 128;
    for (int id = tid; id < BM * 8; id += 256) {
        int r = id >> 3, ck = id & 7;
        u32 so = sw128((u32)(r * 128 + ck * 16));
        size_t g = (size_t)(row0 + r) * K + k0 + ck * 8;
        cpasync16(sbase + so, Ahi + g);
        cpasync16(sbase + ABYTES + so, Alo + g);
    }
    for (int id = tid; id < BN * 8; id += 256) {
        int r = id >> 3, ck = id & 7;
        u32 so = sw128((u32)(r * 128 + ck * 16));
        cpasync16(sbase + 2 * ABYTES + so, Bq + (size_t)(col0 + r) * K + k0 + ck * 8);
    }
    asm volatile("cp.async.commit_group;");
}

template<int BM, int BN, int WM, int WN, int EPI, int WSEL, int ASEL>
__global__ __launch_bounds__(256, 1)
void qgemm_kernel(float* __restrict__ Cout, int layer, int N, int K, int ldc)
{
    constexpr int TM = BM / WM, TN = BN / WN;
    constexpr int MI = TM / 16, NI = TN / 8;
    constexpr u32 STB = (u32)(2 * BM + BN) * 128;

    extern __shared__ char dsm[];
    u32 base = (smem_u32(dsm) + 1023u) & ~1023u;

    int tid = threadIdx.x, lane = tid & 31, wid = tid >> 5;
    int wm = wid % WM, wn = wid / WM;
    int row0 = blockIdx.y * BM, col0 = blockIdx.x * BN;

    const __nv_bfloat16* Ahi = ahisel<ASEL>();
    const __nv_bfloat16* Alo = alosel<ASEL>();
    const __nv_bfloat16* Bq  = qsel<WSEL>() + (size_t)layer * N * K;
    const float* Sc = scsel<WSEL>() + (size_t)layer * N;

    float acc[MI][NI][4];
    #pragma unroll
    for (int mi = 0; mi < MI; mi++) {
        #pragma unroll
        for (int ni = 0; ni < NI; ni++) {
            acc[mi][ni][0] = 0.f; acc[mi][ni][1] = 0.f;
            acc[mi][ni][2] = 0.f; acc[mi][ni][3] = 0.f;
        }
    }

    int n = K >> 6;
    load_stage64<BM, BN>(Ahi, Alo, Bq, base,       row0, col0, K, 0,  tid);
    load_stage64<BM, BN>(Ahi, Alo, Bq, base + STB, row0, col0, K, 64, tid);

    for (int it = 0; it < n; it++) {
        asm volatile("cp.async.wait_group 1;");
        __syncthreads();

        int ldst = it + 2;
        if (ldst < n) {
            int buf = ldst % 3;
            load_stage64<BM, BN>(Ahi, Alo, Bq, base + (u32)buf * STB,
                                 row0, col0, K, ldst << 6, tid);
        } else {
            asm volatile("cp.async.commit_group;");
        }

        u32 sb = base + (u32)(it % 3) * STB;
        #pragma unroll
        for (int kc = 0; kc < 4; kc++) {
            u32 ah[MI][4], al[MI][4];
            #pragma unroll
            for (int mi = 0; mi < MI; mi++) {
                int lr = wm * TM + mi * 16 + (lane & 15);
                int ch = kc * 2 + (lane >> 4);
                u32 so = sw128((u32)(lr * 128 + ch * 16));
                ldm_x4(ah[mi][0], ah[mi][1], ah[mi][2], ah[mi][3], sb + so);
                ldm_x4(al[mi][0], al[mi][1], al[mi][2], al[mi][3], sb + (u32)BM * 128 + so);
            }
            u32 bb[NI][2];
            #pragma unroll
            for (int nj = 0; nj < NI / 2; nj++) {
                int g = lane >> 3;
                int lr = wn * TN + nj * 16 + (((g >> 1) & 1) << 3) + (lane & 7);
                int ch = kc * 2 + (g & 1);
                u32 r0, r1, r2, r3;
                ldm_x4(r0, r1, r2, r3, sb + 2u * BM * 128 + sw128((u32)(lr * 128 + ch * 16)));
                bb[nj * 2][0] = r0; bb[nj * 2][1] = r1;
                bb[nj * 2 + 1][0] = r2; bb[nj * 2 + 1][1] = r3;
            }
            #pragma unroll
            for (int mi = 0; mi < MI; mi++) {
                #pragma unroll
                for (int ni = 0; ni < NI; ni++) {
                    mma16816(acc[mi][ni], ah[mi], bb[ni]);
                    mma16816(acc[mi][ni], al[mi], bb[ni]);
                }
            }
        }
    }

    #pragma unroll
    for (int mi = 0; mi < MI; mi++) {
        #pragma unroll
        for (int ni = 0; ni < NI; ni++) {
            int gr0 = row0 + wm * TM + mi * 16 + (lane >> 2);
            int gc  = col0 + wn * TN + ni * 8 + ((lane & 3) << 1);
            #pragma unroll
            for (int half = 0; half < 2; half++) {
                int gr = gr0 + half * 8;
                #pragma unroll
                for (int e = 0; e < 2; e++) {
                    int c = gc + e;
                    if (c >= N) continue;
                    float v = acc[mi][ni][half * 2 + e] * Sc[c];
                    if (EPI == 0) {
                        g_qkv[(size_t)gr * QKVD_ + c] = v;
                    } else if (EPI == 1) {
                        g_x[(size_t)gr * D_ + c] += v;
                    } else if (EPI == 2) {
                        float t = fmaxf(v, 0.f);
                        split_store(t * t, g_ffhi, g_fflo, (size_t)gr * FF_ + c);
                    } else {
                        Cout[(size_t)gr * ldc + c] = v;
                    }
                }
            }
        }
    }
}

#define DSM_SMALL (3 * (2 * 128 + 64)  * 128 + 1024)
#define DSM_BIG   (3 * (2 * 128 + 128) * 128 + 1024)

// ---------------- host orchestration ----------------
extern "C" void kernel_launch(void* const* d_in, const int* in_sizes, int n_in,
                              void* d_out, int out_size)
{
    (void)in_sizes; (void)n_in; (void)out_size;
    const int*   idx = (const int*)  d_in[0];
    const float* emb = (const float*)d_in[1];
    const float* wq  = (const float*)d_in[2];
    const float* wk  = (const float*)d_in[3];
    const float* wv  = (const float*)d_in[4];
    const float* wo  = (const float*)d_in[5];
    const float* qg  = (const float*)d_in[6];
    const float* wfc = (const float*)d_in[7];
    const float* wpr = (const float*)d_in[8];
    const float* lm  = (const float*)d_in[9];
    float* out = (float*)d_out;

    cudaFuncSetAttribute(qgemm_kernel<128, 64, 4, 2, 0, 0, 0>,
                         cudaFuncAttributeMaxDynamicSharedMemorySize, DSM_SMALL);
    cudaFuncSetAttribute(qgemm_kernel<128, 64, 4, 2, 1, 1, 1>,
                         cudaFuncAttributeMaxDynamicSharedMemorySize, DSM_SMALL);
    cudaFuncSetAttribute(qgemm_kernel<128, 128, 2, 4, 2, 2, 0>,
                         cudaFuncAttributeMaxDynamicSharedMemorySize, DSM_BIG);
    cudaFuncSetAttribute(qgemm_kernel<128, 64, 4, 2, 1, 3, 2>,
                         cudaFuncAttributeMaxDynamicSharedMemorySize, DSM_SMALL);
    cudaFuncSetAttribute(qgemm_kernel<128, 128, 2, 4, 3, 4, 0>,
                         cudaFuncAttributeMaxDynamicSharedMemorySize, DSM_BIG);
    cudaFuncSetAttribute(flash_kernel,
                         cudaFuncAttributeMaxDynamicSharedMemorySize, FA_DSM);

    quant_kernel<0, 4><<<L_ * D_,    256>>>(wq,  D_,   QKVD_, 0);
    quant_kernel<0, 4><<<L_ * KVD_,  256>>>(wk,  KVD_, QKVD_, 1024);
    quant_kernel<0, 4><<<L_ * KVD_,  256>>>(wv,  KVD_, QKVD_, 1280);
    quant_kernel<1, 4><<<L_ * D_,    256>>>(wo,  L_ * D_,  0, 0);
    quant_kernel<2, 4><<<L_ * FF_,   256>>>(wfc, L_ * FF_, 0, 0);
    quant_kernel<3, 16><<<L_ * D_,   256>>>(wpr, L_ * D_,  0, 0);
    quant_kernel<4, 4><<<V_,         256>>>(lm,  V_,       0, 0);

    embed_kernel<<<(S_ * D_) / 256, 256>>>(idx, emb);

    for (int l = 0; l < L_; l++) {
        rmsnorm_split_kernel<<<S_, 256>>>();

        qgemm_kernel<128, 64, 4, 2, 0, 0, 0><<<dim3(QKVD_ / 64, S_ / 128), 256, DSM_SMALL>>>(
            nullptr, l, QKVD_, D_, QKVD_);

        qkpost_kernel<<<(S_ * H_)  / 4, 128>>>(qg + l * H_, H_,  0,    1);
        qkpost_kernel<<<(S_ * KV_) / 4, 128>>>(nullptr,     KV_, 1024, 0);
        vtrans_kernel<<<dim3(S_ / 32, KVD_ / 32), dim3(32, 8)>>>();

        flash_kernel<<<dim3(16, H_), 128, FA_DSM>>>();

        qgemm_kernel<128, 64, 4, 2, 1, 1, 1><<<dim3(D_ / 64, S_ / 128), 256, DSM_SMALL>>>(
            nullptr, l, D_, D_, D_);

        rmsnorm_split_kernel<<<S_, 256>>>();

        qgemm_kernel<128, 128, 2, 4, 2, 2, 0><<<dim3(FF_ / 128, S_ / 128), 256, DSM_BIG>>>(
            nullptr, l, FF_, D_, FF_);

        qgemm_kernel<128, 64, 4, 2, 1, 3, 2><<<dim3(D_ / 64, S_ / 128), 256, DSM_SMALL>>>(
            nullptr, l, D_, FF_, D_);
    }

    rmsnorm_split_kernel<<<S_, 256>>>();
    qgemm_kernel<128, 128, 2, 4, 3, 4, 0><<<dim3(VPAD_ / 128, S_ / 128), 256, DSM_BIG>>>(
        out, 0, V_, D_, V_);
}